// round 8
// baseline (speedup 1.0000x reference)
#include <cuda_runtime.h>
#include <math.h>
#include <stdint.h>

#define B_  256
#define L_  256
#define D_  128
#define H_  256
#define G4_ 1024
#define BL_ (B_*L_)

typedef unsigned long long ull;

// ---------------- f32x2 helpers ---------------------------------------------------
#define FMA2(d,a,b,c) asm("fma.rn.f32x2 %0, %1, %2, %3;" : "=l"(d) : "l"(a), "l"(b), "l"(c))
__device__ __forceinline__ ull bcast2(float v){ ull d; asm("mov.b64 %0, {%1, %1};" : "=l"(d) : "f"(v)); return d; }
__device__ __forceinline__ ull pack2(float lo, float hi){ ull d; asm("mov.b64 %0, {%1, %2};" : "=l"(d) : "f"(lo), "f"(hi)); return d; }
__device__ __forceinline__ float2 unpack2(ull d){ float lo,hi; asm("mov.b64 {%0, %1}, %2;" : "=f"(lo), "=f"(hi) : "l"(d)); return make_float2(lo,hi); }

// ---------------- device scratch (static; no allocations anywhere) ----------------
__device__ float g_gamma_h[BL_*H_];            // 64 MB
__device__ float g_alpha  [BL_*D_];            // 32 MB
// cluster-grouped: [bg(32)][t(256)][q(4)][r(8)][nn(256)]
__device__ float g_gpre   [(size_t)BL_*G4_];   // 256 MB
// per-CTA-contiguous: [q(4)][k(256)][nn(256)]
__device__ float g_Whh_q  [H_*G4_];
__device__ float g_WihA_t [D_*G4_];            // [k][n'] permuted
__device__ float g_WihB_t [D_*G4_];            // [k][n'] permuted
__device__ float g_tdh_t  [D_*H_];             // [d][j]
__device__ float g_wc_t   [(2*D_)*D_];         // [k][dn]
__device__ float g_bias   [G4_];               // permuted b_ih+b_hh
__device__ float g_num    [L_];
__device__ float g_den    [L_];

// gate-column permutation: n' = q*256 + g*64 + jj  <->  n = g*256 + q*64 + jj
__device__ __forceinline__ int permN(int np) {
    return ((np >> 6) & 3) * 256 + (np >> 8) * 64 + (np & 63);
}

// ---------------- K0: weight transposes (permuted) + zero g_num -------------------
__global__ void k_prep(const float* __restrict__ W_ih,   const float* __restrict__ W_hh,
                       const float* __restrict__ td_h_W, const float* __restrict__ wc_W,
                       const float* __restrict__ b_ih,   const float* __restrict__ b_hh)
{
    int idx = blockIdx.x * blockDim.x + threadIdx.x;
    int stride = gridDim.x * blockDim.x;
    for (int i = idx; i < H_*G4_; i += stride) {
        int q = i >> 16, k = (i >> 8) & 255, nn = i & 255;
        g_Whh_q[i] = W_hh[permN(q*256 + nn)*H_ + k];
    }
    for (int i = idx; i < D_*G4_; i += stride) {
        int k = i >> 10, np = i & 1023;
        int n = permN(np);
        g_WihA_t[i] = W_ih[n*(2*D_) + k];
        g_WihB_t[i] = W_ih[n*(2*D_) + D_ + k];
    }
    for (int i = idx; i < D_*H_; i += stride) {
        int d = i / H_, j = i % H_;
        g_tdh_t[i] = td_h_W[j*D_ + d];
    }
    for (int i = idx; i < (2*D_)*D_; i += stride) {
        int k = i / D_, dn = i % D_;
        g_wc_t[i] = wc_W[dn*(2*D_) + k];
    }
    for (int i = idx; i < G4_; i += stride) {
        int n = permN(i);
        g_bias[i] = b_ih[n] + b_hh[n];
    }
    for (int i = idx; i < L_;  i += stride) g_num[i] = 0.f;
}

// ---------------- K0b: per-timestep loss denominator ------------------------------
__global__ void k_den(const float* __restrict__ evalm)
{
    int t = blockIdx.x;
    int tid = threadIdx.x;
    float s = 0.f;
    for (int b = 0; b < B_; b++)
        s += evalm[((size_t)b*L_ + t)*D_ + tid];
    #pragma unroll
    for (int off = 16; off > 0; off >>= 1)
        s += __shfl_down_sync(0xffffffffu, s, off);
    __shared__ float red[4];
    if ((tid & 31) == 0) red[tid >> 5] = s;
    __syncthreads();
    if (tid == 0) g_den[t] = red[0] + red[1] + red[2] + red[3];
}

// ---------------- K1: gamma_h precompute -------------------------------------------
__global__ void __launch_bounds__(256) k_gamma_h(const float* __restrict__ deltas,
                                                 const float* __restrict__ td_h_b)
{
    __shared__ float sd[16][D_];
    int bl0 = blockIdx.x * 16;
    int tid = threadIdx.x;
    #pragma unroll
    for (int i = 0; i < 8; i++) {
        int idx = tid + i*256;
        int r = idx >> 7, d = idx & 127;
        sd[r][d] = deltas[(size_t)(bl0 + r)*D_ + d];
    }
    __syncthreads();
    int j = tid;
    float acc[16];
    float b = td_h_b[j];
    #pragma unroll
    for (int r = 0; r < 16; r++) acc[r] = b;
    #pragma unroll 4
    for (int d = 0; d < D_; d++) {
        float w = g_tdh_t[d*H_ + j];
        #pragma unroll
        for (int r = 0; r < 16; r++) acc[r] += sd[r][d] * w;
    }
    #pragma unroll
    for (int r = 0; r < 16; r++)
        g_gamma_h[(size_t)(bl0 + r)*H_ + j] = __expf(-fmaxf(acc[r], 0.f));
}

// ---------------- K2: alpha precompute ---------------------------------------------
__global__ void __launch_bounds__(128) k_alpha(const float* __restrict__ deltas,
                                               const float* __restrict__ masks,
                                               const float* __restrict__ td_x_w,
                                               const float* __restrict__ td_x_b,
                                               const float* __restrict__ wc_b)
{
    __shared__ float sin_[16][2*D_];
    int bl0 = blockIdx.x * 16;
    int tid = threadIdx.x;
    #pragma unroll
    for (int i = 0; i < 32; i++) {
        int idx = tid + i*128;
        int r = idx >> 8, k = idx & 255;
        float v;
        if (k < D_) {
            float dd = deltas[(size_t)(bl0 + r)*D_ + k];
            v = __expf(-fmaxf(dd*td_x_w[k] + td_x_b[k], 0.f));
        } else {
            v = masks[(size_t)(bl0 + r)*D_ + (k - D_)];
        }
        sin_[r][k] = v;
    }
    __syncthreads();
    int dn = tid;
    float acc[16];
    float b = wc_b[dn];
    #pragma unroll
    for (int r = 0; r < 16; r++) acc[r] = b;
    #pragma unroll 4
    for (int k = 0; k < 2*D_; k++) {
        float w = g_wc_t[k*D_ + dn];
        #pragma unroll
        for (int r = 0; r < 16; r++) acc[r] += sin_[r][k] * w;
    }
    #pragma unroll
    for (int r = 0; r < 16; r++)
        g_alpha[(size_t)(bl0 + r)*D_ + dn] = acc[r];
}

// ---------------- K3: gates m-half precompute (cluster-grouped layout) --------------
__global__ void __launch_bounds__(256) k_gpre(const float* __restrict__ masks)
{
    __shared__ float sm[D_*8];      // [d][row]
    int bl0 = blockIdx.x * 8;
    int tid = threadIdx.x;
    #pragma unroll
    for (int i = 0; i < 4; i++) {
        int idx = tid + i*256;
        int r = idx >> 7, d = idx & 127;
        sm[d*8 + r] = masks[(size_t)(bl0 + r)*D_ + d];
    }
    __syncthreads();
    int n4 = tid * 4;
    float4 bias4 = *(const float4*)&g_bias[n4];
    ull acc[4][4];                  // [rowpair][col]
    #pragma unroll
    for (int rp = 0; rp < 4; rp++) {
        acc[rp][0] = bcast2(bias4.x); acc[rp][1] = bcast2(bias4.y);
        acc[rp][2] = bcast2(bias4.z); acc[rp][3] = bcast2(bias4.w);
    }
    #pragma unroll 4
    for (int k = 0; k < D_; k++) {
        float4 w = *(const float4*)&g_WihB_t[k*G4_ + n4];
        ull pw0 = bcast2(w.x), pw1 = bcast2(w.y), pw2 = bcast2(w.z), pw3 = bcast2(w.w);
        ulonglong2 mA = *(const ulonglong2*)&sm[k*8];
        ulonglong2 mB = *(const ulonglong2*)&sm[k*8 + 4];
        FMA2(acc[0][0], mA.x, pw0, acc[0][0]); FMA2(acc[0][1], mA.x, pw1, acc[0][1]);
        FMA2(acc[0][2], mA.x, pw2, acc[0][2]); FMA2(acc[0][3], mA.x, pw3, acc[0][3]);
        FMA2(acc[1][0], mA.y, pw0, acc[1][0]); FMA2(acc[1][1], mA.y, pw1, acc[1][1]);
        FMA2(acc[1][2], mA.y, pw2, acc[1][2]); FMA2(acc[1][3], mA.y, pw3, acc[1][3]);
        FMA2(acc[2][0], mB.x, pw0, acc[2][0]); FMA2(acc[2][1], mB.x, pw1, acc[2][1]);
        FMA2(acc[2][2], mB.x, pw2, acc[2][2]); FMA2(acc[2][3], mB.x, pw3, acc[2][3]);
        FMA2(acc[3][0], mB.y, pw0, acc[3][0]); FMA2(acc[3][1], mB.y, pw1, acc[3][1]);
        FMA2(acc[3][2], mB.y, pw2, acc[3][2]); FMA2(acc[3][3], mB.y, pw3, acc[3][3]);
    }
    int b = bl0 >> 8, t0c = bl0 & 255;
    int bg = b >> 3, r = b & 7;
    int q = tid >> 6, nn = n4 & 255;
    #pragma unroll
    for (int rp = 0; rp < 4; rp++) {
        float2 u0 = unpack2(acc[rp][0]), u1 = unpack2(acc[rp][1]);
        float2 u2 = unpack2(acc[rp][2]), u3 = unpack2(acc[rp][3]);
        float4 lo = make_float4(u0.x, u1.x, u2.x, u3.x);
        float4 hi = make_float4(u0.y, u1.y, u2.y, u3.y);
        size_t aLo = ((((size_t)bg*256 + t0c + 2*rp    )*4 + q)*8 + r)*256 + nn;
        size_t aHi = ((((size_t)bg*256 + t0c + 2*rp + 1)*4 + q)*8 + r)*256 + nn;
        *(float4*)&g_gpre[aLo] = lo;
        *(float4*)&g_gpre[aHi] = hi;
    }
}

// ---------------- DSMEM helpers -----------------------------------------------------
__device__ __forceinline__ uint32_t smem_u32_(const void* p) {
    uint32_t a;
    asm("{ .reg .u64 t; cvta.to.shared.u64 t, %1; cvt.u32.u64 %0, t; }"
        : "=r"(a) : "l"(p));
    return a;
}
__device__ __forceinline__ void st_dsmem(uint32_t addr, float v) {
    asm volatile("st.shared::cluster.f32 [%0], %1;" :: "r"(addr), "f"(v) : "memory");
}
#define CLUSTER_SYNC_() do { \
    asm volatile("barrier.cluster.arrive.aligned;" ::: "memory"); \
    asm volatile("barrier.cluster.wait.aligned;"  ::: "memory"); } while (0)

// SMEM layout (floats)
#define HIST_STRIDE 257
#define FEAT_STRIDE 129
#define SOFF_WIHA  0
#define SOFF_HISTT (SOFF_WIHA + 128*256)                 // 32768
#define SOFF_FEATT (SOFF_HISTT + 32*HIST_STRIDE)         // 40992
#define SOFF_HDA   (SOFF_FEATT + 32*FEAT_STRIDE)         // 45120
#define SOFF_XC    (SOFF_HDA + 2*256*8)                  // 49216
#define SOFF_CC    (SOFF_XC + 128*8)                     // 50240
#define SOFF_GT    (SOFF_CC + 128*8)                     // 51264
#define SOFF_PART  (SOFF_GT + 8*256)                     // 53312  [w(8)][dd(32)][9]
#define SOFF_NUM   (SOFF_PART + 8*32*9)                  // 55616
#define SMEM_FLOATS (SOFF_NUM + 16)
#define SMEM_BYTES (SMEM_FLOATS * 4)

__device__ __forceinline__ float sigm_(float x) { return 1.f / (1.f + __expf(-x)); }
__device__ __forceinline__ float tanh_(float x) { return 2.f / (1.f + __expf(-2.f*x)) - 1.f; }

// ---------------- K4: cluster-4 sequential recurrence (k-split P1/P2) ---------------
__global__ void __launch_bounds__(256) __cluster_dims__(4, 1, 1)
k_main4(const float* __restrict__ values, const float* __restrict__ masks,
        const float* __restrict__ evalm,
        const float* __restrict__ hist_W, const float* __restrict__ feat_W,
        const float* __restrict__ hist_b, const float* __restrict__ feat_b,
        float* __restrict__ out)
{
    extern __shared__ float smf[];
    float* s_wihA  = smf + SOFF_WIHA;    // [128][256]
    float* s_histT = smf + SOFF_HISTT;   // [32][257]  own d-slice rows, k-major
    float* s_featT = smf + SOFF_FEATT;   // [32][129]
    float* s_hdA   = smf + SOFF_HDA;     // [2][256][8]  hd, [k][row]
    float* s_xc    = smf + SOFF_XC;      // [128][8]     xc, [d][row]
    float* s_cc    = smf + SOFF_CC;      // [128][8]     cc, [d][row]
    float* s_gt    = smf + SOFF_GT;      // [8][256]
    float* s_part  = smf + SOFF_PART;    // [8][32][9] reduction scratch
    float* s_num   = smf + SOFF_NUM;

    const int tid = threadIdx.x;
    uint32_t q;
    asm("mov.u32 %0, %%cluster_ctarank;" : "=r"(q));
    const int bg = blockIdx.x >> 2;
    const int b0 = bg * 8;

    // --- preload stationary slices ---
    #pragma unroll 4
    for (int i = tid; i < 128*256; i += 256) {
        int k = i >> 8, nn = i & 255;
        s_wihA[i] = g_WihA_t[k*G4_ + (int)q*256 + nn];
    }
    #pragma unroll 4
    for (int i = tid; i < 32*256; i += 256) {
        int dd = i >> 8, k = i & 255;
        s_histT[dd*HIST_STRIDE + k] = hist_W[((int)q*32 + dd)*H_ + k];
    }
    #pragma unroll 2
    for (int i = tid; i < 32*128; i += 256) {
        int dd = i >> 7, k = i & 127;
        int dg = (int)q*32 + dd;
        s_featT[dd*FEAT_STRIDE + k] = (k == dg) ? 0.f : feat_W[dg*D_ + k];
    }
    if (tid == 0) s_num[0] = 0.f;
    __syncthreads();

    // remote SMEM bases for the 4 ranks
    uint32_t sbase = smem_u32_(smf);
    uint32_t rb0, rb1, rb2, rb3;
    asm("mapa.shared::cluster.u32 %0, %1, %2;" : "=r"(rb0) : "r"(sbase), "r"(0u));
    asm("mapa.shared::cluster.u32 %0, %1, %2;" : "=r"(rb1) : "r"(sbase), "r"(1u));
    asm("mapa.shared::cluster.u32 %0, %1, %2;" : "=r"(rb2) : "r"(sbase), "r"(2u));
    asm("mapa.shared::cluster.u32 %0, %1, %2;" : "=r"(rb3) : "r"(sbase), "r"(3u));

    // thread mappings
    const int r1 = tid >> 5;                 // batch row 0..7 / k-split warp id
    const int dd = tid & 31;                 // within-slice d
    const int dg = (int)q*32 + dd;           // global d
    const int jjA = dd*2;                    // two owned (local) h-indices
    const int jgA = (int)q*64 + jjA;         // global h index
    const float hb = hist_b[dg], fb = feat_b[dg];

    const size_t ib0   = ((size_t)(b0+r1)*L_)*D_ + dg;    // + t*D_
    const size_t gam0  = ((size_t)(b0+r1)*L_)*H_ + jgA;   // + t*H_
    const float* wp    = g_Whh_q + ((size_t)q << 16) + tid;
    const float* gp0   = g_gpre + (((size_t)bg*256*4 + q)*8)*256 + tid;  // + t*4*8*256

    float hA = 0.f, hB = 0.f, cA = 0.f, cB = 0.f;

    // rotated prefetch registers (step 0)
    float2 gg   = *(const float2*)&g_gamma_h[gam0];
    float  xv_n = values[ib0];
    float  mv_n = masks[ib0];
    float  al_n = g_alpha[ib0];
    float  ev_n = evalm[ib0];

    for (int t = 0; t < L_; t++) {
        const int par = t & 1;
        const int tn = (t + 1) & 255;         // wrapped (last iter value unused)

        // ---- gpre prefetch for THIS step (consumed in P3, ~3 phases away) ----
        float g8[8];
        {
            const float* gp = gp0 + (size_t)t*(4*8*256);
            #pragma unroll
            for (int r = 0; r < 8; r++) g8[r] = gp[r*256];
        }

        // ---- P0: decay h, push hd in [k][row] layout (8 stores) ----
        {
            float hdA = hA * gg.x;
            float hdB = hB * gg.y;
            uint32_t oA = (uint32_t)(SOFF_HDA + ((par*256 + jgA)*8 + r1)) * 4u;
            uint32_t oB = oA + 32u;           // jgA+1 -> +8 floats
            st_dsmem(rb0 + oA, hdA); st_dsmem(rb0 + oB, hdB);
            st_dsmem(rb1 + oA, hdA); st_dsmem(rb1 + oB, hdB);
            st_dsmem(rb2 + oA, hdA); st_dsmem(rb2 + oB, hdB);
            st_dsmem(rb3 + oA, hdA); st_dsmem(rb3 + oB, hdB);
            gg = *(const float2*)&g_gamma_h[gam0 + (size_t)tn*H_];
        }
        CLUSTER_SYNC_();

        // ---- P1 (k-split): x_h partials; warp r1 covers k in [32r1, 32r1+32) ----
        const size_t ib = ib0 + (size_t)t*D_;
        const float xv = xv_n;
        const float mv = mv_n;
        {   // prefetch next-step x/m
            const size_t ibn = ib0 + (size_t)tn*D_;
            xv_n = values[ibn];
            mv_n = masks[ibn];
        }
        {
            const int k0 = r1*32;
            const float* wrow = &s_histT[dd*HIST_STRIDE + k0];
            const float* hdp  = &s_hdA[par*2048 + k0*8];
            ull a0 = 0, a1 = 0, a2 = 0, a3 = 0;
            #pragma unroll 8
            for (int kk = 0; kk < 32; kk++) {
                ull ww = bcast2(wrow[kk]);
                ulonglong2 u = *(const ulonglong2*)(hdp + kk*8);
                ulonglong2 v = *(const ulonglong2*)(hdp + kk*8 + 4);
                FMA2(a0, u.x, ww, a0); FMA2(a1, u.y, ww, a1);
                FMA2(a2, v.x, ww, a2); FMA2(a3, v.y, ww, a3);
            }
            float* pp = &s_part[(r1*32 + dd)*9];
            float2 t0 = unpack2(a0), t1 = unpack2(a1), t2 = unpack2(a2), t3 = unpack2(a3);
            pp[0]=t0.x; pp[1]=t0.y; pp[2]=t1.x; pp[3]=t1.y;
            pp[4]=t2.x; pp[5]=t2.y; pp[6]=t3.x; pp[7]=t3.y;
        }
        __syncthreads();
        float xh;
        {
            xh = hb;
            #pragma unroll
            for (int w = 0; w < 8; w++) xh += s_part[(w*32 + dd)*9 + r1];
        }
        const float xc = mv*xv + (1.f - mv)*xh;
        {
            uint32_t o = (uint32_t)(SOFF_XC + (dg*8 + r1)) * 4u;
            st_dsmem(rb0 + o, xc); st_dsmem(rb1 + o, xc);
            st_dsmem(rb2 + o, xc); st_dsmem(rb3 + o, xc);
        }
        CLUSTER_SYNC_();

        // ---- P2 (k-split): z_h partials; warp r1 covers k in [16r1, 16r1+16) ----
        {
            const int k0 = r1*16;
            const float* wrow = &s_featT[dd*FEAT_STRIDE + k0];
            const float* xp   = &s_xc[k0*8];
            ull a0 = 0, a1 = 0, a2 = 0, a3 = 0;
            #pragma unroll 8
            for (int kk = 0; kk < 16; kk++) {
                ull ww = bcast2(wrow[kk]);
                ulonglong2 u = *(const ulonglong2*)(xp + kk*8);
                ulonglong2 v = *(const ulonglong2*)(xp + kk*8 + 4);
                FMA2(a0, u.x, ww, a0); FMA2(a1, u.y, ww, a1);
                FMA2(a2, v.x, ww, a2); FMA2(a3, v.y, ww, a3);
            }
            float* pp = &s_part[(r1*32 + dd)*9];
            float2 t0 = unpack2(a0), t1 = unpack2(a1), t2 = unpack2(a2), t3 = unpack2(a3);
            pp[0]=t0.x; pp[1]=t0.y; pp[2]=t1.x; pp[3]=t1.y;
            pp[4]=t2.x; pp[5]=t2.y; pp[6]=t3.x; pp[7]=t3.y;
        }
        __syncthreads();
        float cc;
        {
            float zh = fb;
            #pragma unroll
            for (int w = 0; w < 8; w++) zh += s_part[(w*32 + dd)*9 + r1];
            const float al = al_n;
            const float me = ev_n;
            {   // prefetch next-step alpha/evalm
                const size_t ibn = ib0 + (size_t)tn*D_;
                al_n = g_alpha[ibn];
                ev_n = evalm[ibn];
            }
            float ch = al*zh + (1.f - al)*xh;
            cc = mv*xv + (1.f - mv)*ch;
            out[ib] = cc;
            float p = fabsf(cc - xv) * me;
            #pragma unroll
            for (int off = 16; off > 0; off >>= 1)
                p += __shfl_down_sync(0xffffffffu, p, off);
            if (dd == 0) atomicAdd(s_num, p);
            uint32_t o = (uint32_t)(SOFF_CC + (dg*8 + r1)) * 4u;
            st_dsmem(rb0 + o, cc); st_dsmem(rb1 + o, cc);
            st_dsmem(rb2 + o, cc); st_dsmem(rb3 + o, cc);
        }
        CLUSTER_SYNC_();

        // ---- P3: gates = gpre + hd@Whh-slice + cc@WihA-slice (own 256 n') ----
        if (tid == 0) {
            atomicAdd(&g_num[t], s_num[0]);
            s_num[0] = 0.f;
        }
        {
            ull acc[4];
            acc[0] = pack2(g8[0], g8[1]); acc[1] = pack2(g8[2], g8[3]);
            acc[2] = pack2(g8[4], g8[5]); acc[3] = pack2(g8[6], g8[7]);
            {
                const float* hdp = &s_hdA[par*2048];
                #pragma unroll 16
                for (int k = 0; k < 256; k++) {
                    ull ww = bcast2(wp[k*256]);           // contiguous-k L2 stream
                    ulonglong2 u = *(const ulonglong2*)(hdp + k*8);
                    ulonglong2 v = *(const ulonglong2*)(hdp + k*8 + 4);
                    FMA2(acc[0], u.x, ww, acc[0]);
                    FMA2(acc[1], u.y, ww, acc[1]);
                    FMA2(acc[2], v.x, ww, acc[2]);
                    FMA2(acc[3], v.y, ww, acc[3]);
                }
            }
            {
                #pragma unroll 8
                for (int k = 0; k < 128; k++) {
                    ull ww = bcast2(s_wihA[k*256 + tid]);
                    ulonglong2 u = *(const ulonglong2*)(s_cc + k*8);
                    ulonglong2 v = *(const ulonglong2*)(s_cc + k*8 + 4);
                    FMA2(acc[0], u.x, ww, acc[0]);
                    FMA2(acc[1], u.y, ww, acc[1]);
                    FMA2(acc[2], v.x, ww, acc[2]);
                    FMA2(acc[3], v.y, ww, acc[3]);
                }
            }
            #pragma unroll
            for (int rp = 0; rp < 4; rp++) {
                float2 u = unpack2(acc[rp]);
                s_gt[(2*rp    )*256 + tid] = u.x;
                s_gt[(2*rp + 1)*256 + tid] = u.y;
            }
        }
        __syncthreads();

        // ---- P4: LSTM elementwise for (row r1, local j = jjA, jjA+1) ----
        {
            const float* gr = &s_gt[r1*256];
            float2 ii = *(const float2*)(gr + jjA);
            float2 ff = *(const float2*)(gr + 64 + jjA);
            float2 gv = *(const float2*)(gr + 128 + jjA);
            float2 oo = *(const float2*)(gr + 192 + jjA);
            float i0 = sigm_(ii.x), f0 = sigm_(ff.x), o0 = sigm_(oo.x), g0 = tanh_(gv.x);
            float i1 = sigm_(ii.y), f1 = sigm_(ff.y), o1 = sigm_(oo.y), g1 = tanh_(gv.y);
            cA = f0*cA + i0*g0;  hA = o0 * tanh_(cA);
            cB = f1*cB + i1*g1;  hB = o1 * tanh_(cB);
        }
        // s_hdA double-buffered (par); s_xc/s_cc/s_gt/s_part rewrites are
        // separated by >=1 cluster sync (or CTA barrier) from their last reads.
    }
}

// ---------------- K5: finalize loss -------------------------------------------------
__global__ void k_fin(float* __restrict__ out, int out_size)
{
    int t = threadIdx.x;
    float v = g_num[t] / (g_den[t] + 1e-5f);
    #pragma unroll
    for (int off = 16; off > 0; off >>= 1)
        v += __shfl_down_sync(0xffffffffu, v, off);
    __shared__ float red[8];
    if ((t & 31) == 0) red[t >> 5] = v;
    __syncthreads();
    if (t == 0) {
        float s = 0.f;
        #pragma unroll
        for (int i = 0; i < 8; i++) s += red[i];
        if (out_size > B_*L_*D_) out[B_*L_*D_] = s;
    }
}

// ---------------- launch -------------------------------------------------------------
extern "C" void kernel_launch(void* const* d_in, const int* in_sizes, int n_in,
                              void* d_out, int out_size)
{
    const float* values = (const float*)d_in[0];
    const float* masks  = (const float*)d_in[1];
    const float* deltas = (const float*)d_in[2];
    const float* evalm  = (const float*)d_in[3];
    const float* td_h_W = (const float*)d_in[4];
    const float* td_h_b = (const float*)d_in[5];
    const float* td_x_w = (const float*)d_in[6];
    const float* td_x_b = (const float*)d_in[7];
    const float* hist_W = (const float*)d_in[8];
    const float* hist_b = (const float*)d_in[9];
    const float* feat_W = (const float*)d_in[10];
    const float* feat_b = (const float*)d_in[11];
    const float* wc_W   = (const float*)d_in[12];
    const float* wc_b   = (const float*)d_in[13];
    const float* W_ih   = (const float*)d_in[14];
    const float* W_hh   = (const float*)d_in[15];
    const float* b_ih   = (const float*)d_in[16];
    const float* b_hh   = (const float*)d_in[17];
    float* out = (float*)d_out;

    cudaFuncSetAttribute(k_main4, cudaFuncAttributeMaxDynamicSharedMemorySize, SMEM_BYTES);

    k_prep   <<<256, 256>>>(W_ih, W_hh, td_h_W, wc_W, b_ih, b_hh);
    k_den    <<<L_, 128>>>(evalm);
    k_gamma_h<<<BL_/16, 256>>>(deltas, td_h_b);
    k_alpha  <<<BL_/16, 128>>>(deltas, masks, td_x_w, td_x_b, wc_b);
    k_gpre   <<<BL_/8, 256>>>(masks);
    k_main4  <<<128, 256, SMEM_BYTES>>>(values, masks, evalm, hist_W, feat_W,
                                        hist_b, feat_b, out);
    k_fin    <<<1, 256>>>(out, out_size);
}

// round 9
// speedup vs baseline: 1.5426x; 1.5426x over previous
#include <cuda_runtime.h>
#include <math.h>
#include <stdint.h>

#define B_  256
#define L_  256
#define D_  128
#define H_  256
#define G4_ 1024
#define BL_ (B_*L_)

typedef unsigned long long ull;

// ---------------- f32x2 helpers ---------------------------------------------------
#define FMA2(d,a,b,c) asm("fma.rn.f32x2 %0, %1, %2, %3;" : "=l"(d) : "l"(a), "l"(b), "l"(c))
__device__ __forceinline__ ull bcast2(float v){ ull d; asm("mov.b64 %0, {%1, %1};" : "=l"(d) : "f"(v)); return d; }
__device__ __forceinline__ ull pack2(float lo, float hi){ ull d; asm("mov.b64 %0, {%1, %2};" : "=l"(d) : "f"(lo), "f"(hi)); return d; }
__device__ __forceinline__ float2 unpack2(ull d){ float lo,hi; asm("mov.b64 {%0, %1}, %2;" : "=f"(lo), "=f"(hi) : "l"(d)); return make_float2(lo,hi); }

// ---------------- device scratch (static; no allocations anywhere) ----------------
__device__ float g_gamma_h[BL_*H_];            // 64 MB
__device__ float g_alpha  [BL_*D_];            // 32 MB
// cluster-grouped: [bg(32)][t(256)][q(4)][r(8)][nn(256)]
__device__ float g_gpre   [(size_t)BL_*G4_];   // 256 MB
// per-CTA-contiguous: [q(4)][k(256)][nn(256)]
__device__ float g_Whh_q  [H_*G4_];
__device__ float g_WihA_t [D_*G4_];            // [k][n'] permuted
__device__ float g_WihB_t [D_*G4_];            // [k][n'] permuted
__device__ float g_tdh_t  [D_*H_];             // [d][j]
__device__ float g_wc_t   [(2*D_)*D_];         // [k][dn]
__device__ float g_bias   [G4_];               // permuted b_ih+b_hh
__device__ float g_num    [L_];
__device__ float g_den    [L_];

// gate-column permutation: n' = q*256 + g*64 + jj  <->  n = g*256 + q*64 + jj
__device__ __forceinline__ int permN(int np) {
    return ((np >> 6) & 3) * 256 + (np >> 8) * 64 + (np & 63);
}

// ---------------- K0: weight transposes (permuted) + zero g_num -------------------
__global__ void k_prep(const float* __restrict__ W_ih,   const float* __restrict__ W_hh,
                       const float* __restrict__ td_h_W, const float* __restrict__ wc_W,
                       const float* __restrict__ b_ih,   const float* __restrict__ b_hh)
{
    int idx = blockIdx.x * blockDim.x + threadIdx.x;
    int stride = gridDim.x * blockDim.x;
    for (int i = idx; i < H_*G4_; i += stride) {
        int q = i >> 16, k = (i >> 8) & 255, nn = i & 255;
        g_Whh_q[i] = W_hh[permN(q*256 + nn)*H_ + k];
    }
    for (int i = idx; i < D_*G4_; i += stride) {
        int k = i >> 10, np = i & 1023;
        int n = permN(np);
        g_WihA_t[i] = W_ih[n*(2*D_) + k];
        g_WihB_t[i] = W_ih[n*(2*D_) + D_ + k];
    }
    for (int i = idx; i < D_*H_; i += stride) {
        int d = i / H_, j = i % H_;
        g_tdh_t[i] = td_h_W[j*D_ + d];
    }
    for (int i = idx; i < (2*D_)*D_; i += stride) {
        int k = i / D_, dn = i % D_;
        g_wc_t[i] = wc_W[dn*(2*D_) + k];
    }
    for (int i = idx; i < G4_; i += stride) {
        int n = permN(i);
        g_bias[i] = b_ih[n] + b_hh[n];
    }
    for (int i = idx; i < L_;  i += stride) g_num[i] = 0.f;
}

// ---------------- K0b: per-timestep loss denominator ------------------------------
__global__ void k_den(const float* __restrict__ evalm)
{
    int t = blockIdx.x;
    int tid = threadIdx.x;
    float s = 0.f;
    for (int b = 0; b < B_; b++)
        s += evalm[((size_t)b*L_ + t)*D_ + tid];
    #pragma unroll
    for (int off = 16; off > 0; off >>= 1)
        s += __shfl_down_sync(0xffffffffu, s, off);
    __shared__ float red[4];
    if ((tid & 31) == 0) red[tid >> 5] = s;
    __syncthreads();
    if (tid == 0) g_den[t] = red[0] + red[1] + red[2] + red[3];
}

// ---------------- K1: gamma_h precompute -------------------------------------------
__global__ void __launch_bounds__(256) k_gamma_h(const float* __restrict__ deltas,
                                                 const float* __restrict__ td_h_b)
{
    __shared__ float sd[16][D_];
    int bl0 = blockIdx.x * 16;
    int tid = threadIdx.x;
    #pragma unroll
    for (int i = 0; i < 8; i++) {
        int idx = tid + i*256;
        int r = idx >> 7, d = idx & 127;
        sd[r][d] = deltas[(size_t)(bl0 + r)*D_ + d];
    }
    __syncthreads();
    int j = tid;
    float acc[16];
    float b = td_h_b[j];
    #pragma unroll
    for (int r = 0; r < 16; r++) acc[r] = b;
    #pragma unroll 4
    for (int d = 0; d < D_; d++) {
        float w = g_tdh_t[d*H_ + j];
        #pragma unroll
        for (int r = 0; r < 16; r++) acc[r] += sd[r][d] * w;
    }
    #pragma unroll
    for (int r = 0; r < 16; r++)
        g_gamma_h[(size_t)(bl0 + r)*H_ + j] = __expf(-fmaxf(acc[r], 0.f));
}

// ---------------- K2: alpha precompute ---------------------------------------------
__global__ void __launch_bounds__(128) k_alpha(const float* __restrict__ deltas,
                                               const float* __restrict__ masks,
                                               const float* __restrict__ td_x_w,
                                               const float* __restrict__ td_x_b,
                                               const float* __restrict__ wc_b)
{
    __shared__ float sin_[16][2*D_];
    int bl0 = blockIdx.x * 16;
    int tid = threadIdx.x;
    #pragma unroll
    for (int i = 0; i < 32; i++) {
        int idx = tid + i*128;
        int r = idx >> 8, k = idx & 255;
        float v;
        if (k < D_) {
            float dd = deltas[(size_t)(bl0 + r)*D_ + k];
            v = __expf(-fmaxf(dd*td_x_w[k] + td_x_b[k], 0.f));
        } else {
            v = masks[(size_t)(bl0 + r)*D_ + (k - D_)];
        }
        sin_[r][k] = v;
    }
    __syncthreads();
    int dn = tid;
    float acc[16];
    float b = wc_b[dn];
    #pragma unroll
    for (int r = 0; r < 16; r++) acc[r] = b;
    #pragma unroll 4
    for (int k = 0; k < 2*D_; k++) {
        float w = g_wc_t[k*D_ + dn];
        #pragma unroll
        for (int r = 0; r < 16; r++) acc[r] += sin_[r][k] * w;
    }
    #pragma unroll
    for (int r = 0; r < 16; r++)
        g_alpha[(size_t)(bl0 + r)*D_ + dn] = acc[r];
}

// ---------------- K3: gates m-half precompute (16 rows/CTA, halved L2 traffic) -----
__global__ void __launch_bounds__(512) k_gpre(const float* __restrict__ masks)
{
    __shared__ float sm[D_*16];     // [d][row16]
    int bl0 = blockIdx.x * 16;      // 16 consecutive bl = same b (256|16), t0..t0+15
    int tid = threadIdx.x;
    #pragma unroll
    for (int i = 0; i < 4; i++) {
        int idx = tid + i*512;
        int r = idx >> 7, d = idx & 127;
        sm[d*16 + r] = masks[(size_t)(bl0 + r)*D_ + d];
    }
    __syncthreads();
    int n2 = tid * 2;               // two owned permuted columns
    float2 b2 = *(const float2*)&g_bias[n2];
    ull acc[8][2];                  // [rowpair][col]
    #pragma unroll
    for (int rp = 0; rp < 8; rp++) { acc[rp][0] = bcast2(b2.x); acc[rp][1] = bcast2(b2.y); }
    #pragma unroll 2
    for (int k = 0; k < D_; k++) {
        float2 w = *(const float2*)&g_WihB_t[k*G4_ + n2];
        ull pw0 = bcast2(w.x), pw1 = bcast2(w.y);
        const ulonglong2* mrow = (const ulonglong2*)&sm[k*16];   // broadcast reads
        ulonglong2 m0 = mrow[0], m1 = mrow[1], m2 = mrow[2], m3 = mrow[3];
        FMA2(acc[0][0], m0.x, pw0, acc[0][0]); FMA2(acc[0][1], m0.x, pw1, acc[0][1]);
        FMA2(acc[1][0], m0.y, pw0, acc[1][0]); FMA2(acc[1][1], m0.y, pw1, acc[1][1]);
        FMA2(acc[2][0], m1.x, pw0, acc[2][0]); FMA2(acc[2][1], m1.x, pw1, acc[2][1]);
        FMA2(acc[3][0], m1.y, pw0, acc[3][0]); FMA2(acc[3][1], m1.y, pw1, acc[3][1]);
        FMA2(acc[4][0], m2.x, pw0, acc[4][0]); FMA2(acc[4][1], m2.x, pw1, acc[4][1]);
        FMA2(acc[5][0], m2.y, pw0, acc[5][0]); FMA2(acc[5][1], m2.y, pw1, acc[5][1]);
        FMA2(acc[6][0], m3.x, pw0, acc[6][0]); FMA2(acc[6][1], m3.x, pw1, acc[6][1]);
        FMA2(acc[7][0], m3.y, pw0, acc[7][0]); FMA2(acc[7][1], m3.y, pw1, acc[7][1]);
    }
    // write cluster-grouped: [bg][t][q][r][nn]
    int b = bl0 >> 8, t0c = bl0 & 255;
    int bg = b >> 3, rr = b & 7;
    int q = n2 >> 8, nn = n2 & 255;
    #pragma unroll
    for (int rp = 0; rp < 8; rp++) {
        float2 u0 = unpack2(acc[rp][0]), u1 = unpack2(acc[rp][1]);
        float2 lo = make_float2(u0.x, u1.x);
        float2 hi = make_float2(u0.y, u1.y);
        size_t aLo = ((((size_t)bg*256 + t0c + 2*rp    )*4 + q)*8 + rr)*256 + nn;
        size_t aHi = ((((size_t)bg*256 + t0c + 2*rp + 1)*4 + q)*8 + rr)*256 + nn;
        *(float2*)&g_gpre[aLo] = lo;
        *(float2*)&g_gpre[aHi] = hi;
    }
}

// ---------------- DSMEM helpers -----------------------------------------------------
__device__ __forceinline__ uint32_t smem_u32_(const void* p) {
    uint32_t a;
    asm("{ .reg .u64 t; cvta.to.shared.u64 t, %1; cvt.u32.u64 %0, t; }"
        : "=r"(a) : "l"(p));
    return a;
}
__device__ __forceinline__ void st_dsmem(uint32_t addr, float v) {
    asm volatile("st.shared::cluster.f32 [%0], %1;" :: "r"(addr), "f"(v) : "memory");
}
__device__ __forceinline__ void st_dsmem64(uint32_t addr, ull v) {
    asm volatile("st.shared::cluster.b64 [%0], %1;" :: "r"(addr), "l"(v) : "memory");
}
#define CLUSTER_SYNC_() do { \
    asm volatile("barrier.cluster.arrive.aligned;" ::: "memory"); \
    asm volatile("barrier.cluster.wait.aligned;"  ::: "memory"); } while (0)

// SMEM layout (floats)
#define HIST_STRIDE 260
#define FEAT_STRIDE 132
#define SOFF_WIHA  0
#define SOFF_HISTT (SOFF_WIHA + 128*256)                 // 32768
#define SOFF_FEATT (SOFF_HISTT + 32*HIST_STRIDE)         // 41088
#define SOFF_HDA   (SOFF_FEATT + 32*FEAT_STRIDE)         // 45312
#define SOFF_HDB   (SOFF_HDA + 2*256*8)                  // 49408
#define SOFF_XCB   (SOFF_HDB + 8*256)                    // 51456
#define SOFF_CC    (SOFF_XCB + 8*128)                    // 52480
#define SOFF_GT    (SOFF_CC + 128*8)                     // 53504
#define SOFF_NUM   (SOFF_GT + 8*256)                     // 55552
#define SMEM_FLOATS (SOFF_NUM + 16)
#define SMEM_BYTES (SMEM_FLOATS * 4)

__device__ __forceinline__ float sigm_(float x) { return 1.f / (1.f + __expf(-x)); }
__device__ __forceinline__ float tanh_(float x) { return 2.f / (1.f + __expf(-2.f*x)) - 1.f; }

// ---------------- K4: cluster-4 sequential recurrence (R6 structure + .cs hints) ----
__global__ void __launch_bounds__(256) __cluster_dims__(4, 1, 1)
k_main4(const float* __restrict__ values, const float* __restrict__ masks,
        const float* __restrict__ evalm,
        const float* __restrict__ hist_W, const float* __restrict__ feat_W,
        const float* __restrict__ hist_b, const float* __restrict__ feat_b,
        float* __restrict__ out)
{
    extern __shared__ float smf[];
    float* s_wihA  = smf + SOFF_WIHA;    // [128][256]
    float* s_histT = smf + SOFF_HISTT;   // [32][260]
    float* s_featT = smf + SOFF_FEATT;   // [32][132]
    float* s_hdA   = smf + SOFF_HDA;     // [2][256][8]
    float* s_hdB   = smf + SOFF_HDB;     // [8][256]
    float* s_xcB   = smf + SOFF_XCB;     // [8][128]
    float* s_cc    = smf + SOFF_CC;      // [128][8]
    float* s_gt    = smf + SOFF_GT;      // [8][256]
    float* s_num   = smf + SOFF_NUM;

    const int tid = threadIdx.x;
    uint32_t q;
    asm("mov.u32 %0, %%cluster_ctarank;" : "=r"(q));
    const int bg = blockIdx.x >> 2;
    const int b0 = bg * 8;

    // --- preload stationary slices ---
    #pragma unroll 4
    for (int i = tid; i < 128*256; i += 256) {
        int k = i >> 8, nn = i & 255;
        s_wihA[i] = g_WihA_t[k*G4_ + (int)q*256 + nn];
    }
    #pragma unroll 4
    for (int i = tid; i < 32*256; i += 256) {
        int dd = i >> 8, k = i & 255;
        s_histT[dd*HIST_STRIDE + k] = hist_W[((int)q*32 + dd)*H_ + k];
    }
    #pragma unroll 2
    for (int i = tid; i < 32*128; i += 256) {
        int dd = i >> 7, k = i & 127;
        int dg = (int)q*32 + dd;
        s_featT[dd*FEAT_STRIDE + k] = (k == dg) ? 0.f : feat_W[dg*D_ + k];
    }
    if (tid == 0) s_num[0] = 0.f;
    __syncthreads();

    // remote SMEM bases for the 4 ranks
    uint32_t sbase = smem_u32_(smf);
    uint32_t rb0, rb1, rb2, rb3;
    asm("mapa.shared::cluster.u32 %0, %1, %2;" : "=r"(rb0) : "r"(sbase), "r"(0u));
    asm("mapa.shared::cluster.u32 %0, %1, %2;" : "=r"(rb1) : "r"(sbase), "r"(1u));
    asm("mapa.shared::cluster.u32 %0, %1, %2;" : "=r"(rb2) : "r"(sbase), "r"(2u));
    asm("mapa.shared::cluster.u32 %0, %1, %2;" : "=r"(rb3) : "r"(sbase), "r"(3u));

    // thread mappings
    const int r1 = tid >> 5;                 // batch row 0..7 (one per warp)
    const int dd = tid & 31;                 // within-slice d
    const int dg = (int)q*32 + dd;           // global d
    const int jjA = dd*2;                    // two owned (local) h-indices
    const int jgA = (int)q*64 + jjA;         // global h index
    const float hb = hist_b[dg], fb = feat_b[dg];

    const size_t ib0   = ((size_t)(b0+r1)*L_)*D_ + dg;    // + t*D_
    const size_t gam0  = ((size_t)(b0+r1)*L_)*H_ + jgA;   // + t*H_
    const float* wp    = g_Whh_q + ((size_t)q << 16) + tid;
    const float* gp0   = g_gpre + (((size_t)bg*256*4 + q)*8)*256 + tid;  // + t*4*8*256

    float hA = 0.f, hB = 0.f, cA = 0.f, cB = 0.f;

    // rotated prefetch registers (step 0)
    float2 gg   = __ldcs((const float2*)&g_gamma_h[gam0]);
    float  xv_n = __ldcs(&values[ib0]);
    float  mv_n = __ldcs(&masks[ib0]);
    float  al_n = __ldcs(&g_alpha[ib0]);
    float  ev_n = __ldcs(&evalm[ib0]);

    for (int t = 0; t < L_; t++) {
        const int par = t & 1;
        const int tn = (t + 1) & 255;         // wrapped (last iter value unused)

        // ---- gpre prefetch for THIS step (consumed in P3, ~3 phases away) ----
        float g8[8];
        {
            const float* gp = gp0 + (size_t)t*(4*8*256);
            #pragma unroll
            for (int r = 0; r < 8; r++) g8[r] = __ldcs(gp + r*256);
        }

        // ---- P0: decay h, push hd (layouts A [k][row] and B [row][k]) ----
        {
            float hdA = hA * gg.x;
            float hdB = hB * gg.y;
            uint32_t oA = (uint32_t)(SOFF_HDA + ((par*256 + jgA)*8 + r1)) * 4u;
            uint32_t oA2 = oA + 32u;
            ull hp = pack2(hdA, hdB);
            uint32_t oB = (uint32_t)(SOFF_HDB + (r1*256 + jgA)) * 4u;
            st_dsmem(rb0 + oA, hdA); st_dsmem(rb0 + oA2, hdB); st_dsmem64(rb0 + oB, hp);
            st_dsmem(rb1 + oA, hdA); st_dsmem(rb1 + oA2, hdB); st_dsmem64(rb1 + oB, hp);
            st_dsmem(rb2 + oA, hdA); st_dsmem(rb2 + oA2, hdB); st_dsmem64(rb2 + oB, hp);
            st_dsmem(rb3 + oA, hdA); st_dsmem(rb3 + oA2, hdB); st_dsmem64(rb3 + oB, hp);
            // prefetch next-step gamma (full-step slack)
            gg = __ldcs((const float2*)&g_gamma_h[gam0 + (size_t)tn*H_]);
        }
        CLUSTER_SYNC_();

        // ---- P1: x_h = hd . hist_row(dg) ; xc ; push xc ----
        const size_t ib = ib0 + (size_t)t*D_;
        const float xv = xv_n;
        const float mv = mv_n;
        {   // prefetch next-step x/m
            const size_t ibn = ib0 + (size_t)tn*D_;
            xv_n = __ldcs(&values[ibn]);
            mv_n = __ldcs(&masks[ibn]);
        }
        float xh;
        {
            const float* hp = &s_hdB[r1*256];
            const float* wpt = &s_histT[dd*HIST_STRIDE];
            ull a0 = 0, a1 = 0, a2 = 0, a3 = 0;
            #pragma unroll 8
            for (int k = 0; k < 256; k += 8) {
                ulonglong2 hv  = *(const ulonglong2*)(hp + k);
                ulonglong2 hv2 = *(const ulonglong2*)(hp + k + 4);
                ulonglong2 wv  = *(const ulonglong2*)(wpt + k);
                ulonglong2 wv2 = *(const ulonglong2*)(wpt + k + 4);
                FMA2(a0, hv.x,  wv.x,  a0);
                FMA2(a1, hv.y,  wv.y,  a1);
                FMA2(a2, hv2.x, wv2.x, a2);
                FMA2(a3, hv2.y, wv2.y, a3);
            }
            float2 p0 = unpack2(a0), p1 = unpack2(a1), p2 = unpack2(a2), p3 = unpack2(a3);
            xh = hb + ((p0.x + p0.y) + (p1.x + p1.y)) + ((p2.x + p2.y) + (p3.x + p3.y));
        }
        const float xc = mv*xv + (1.f - mv)*xh;
        {
            uint32_t o = (uint32_t)(SOFF_XCB + (r1*128 + dg)) * 4u;
            st_dsmem(rb0 + o, xc); st_dsmem(rb1 + o, xc);
            st_dsmem(rb2 + o, xc); st_dsmem(rb3 + o, xc);
        }
        CLUSTER_SYNC_();

        // ---- P2: z_h, c_h, c_c, imputation out, loss; push cc ----
        float cc;
        {
            const float al = al_n;
            const float me = ev_n;
            {   // prefetch next-step alpha/evalm
                const size_t ibn = ib0 + (size_t)tn*D_;
                al_n = __ldcs(&g_alpha[ibn]);
                ev_n = __ldcs(&evalm[ibn]);
            }
            const float* xp = &s_xcB[r1*128];
            const float* wpt = &s_featT[dd*FEAT_STRIDE];
            ull a0 = 0, a1 = 0;
            #pragma unroll 8
            for (int k = 0; k < 128; k += 4) {
                ulonglong2 xv2 = *(const ulonglong2*)(xp + k);
                ulonglong2 wv2 = *(const ulonglong2*)(wpt + k);
                FMA2(a0, xv2.x, wv2.x, a0);
                FMA2(a1, xv2.y, wv2.y, a1);
            }
            float2 p0 = unpack2(a0), p1 = unpack2(a1);
            float zh = fb + (p0.x + p0.y) + (p1.x + p1.y);
            float ch = al*zh + (1.f - al)*xh;
            cc = mv*xv + (1.f - mv)*ch;
            __stcs(&out[ib], cc);
            float p = fabsf(cc - xv) * me;
            #pragma unroll
            for (int off = 16; off > 0; off >>= 1)
                p += __shfl_down_sync(0xffffffffu, p, off);
            if (dd == 0) atomicAdd(s_num, p);
            uint32_t o = (uint32_t)(SOFF_CC + (dg*8 + r1)) * 4u;
            st_dsmem(rb0 + o, cc); st_dsmem(rb1 + o, cc);
            st_dsmem(rb2 + o, cc); st_dsmem(rb3 + o, cc);
        }
        CLUSTER_SYNC_();

        // ---- P3: gates = gpre + hd@Whh-slice + cc@WihA-slice (own 256 n') ----
        if (tid == 0) {
            atomicAdd(&g_num[t], s_num[0]);
            s_num[0] = 0.f;
        }
        {
            ull acc[4];
            acc[0] = pack2(g8[0], g8[1]); acc[1] = pack2(g8[2], g8[3]);
            acc[2] = pack2(g8[4], g8[5]); acc[3] = pack2(g8[6], g8[7]);
            {
                const float* hdp = &s_hdA[par*256*8];
                #pragma unroll 16
                for (int k = 0; k < 256; k++) {
                    ull ww = bcast2(wp[k*256]);           // contiguous-k L2 stream
                    ulonglong2 u = *(const ulonglong2*)(hdp + k*8);
                    ulonglong2 v = *(const ulonglong2*)(hdp + k*8 + 4);
                    FMA2(acc[0], u.x, ww, acc[0]);
                    FMA2(acc[1], u.y, ww, acc[1]);
                    FMA2(acc[2], v.x, ww, acc[2]);
                    FMA2(acc[3], v.y, ww, acc[3]);
                }
            }
            {
                #pragma unroll 8
                for (int k = 0; k < 128; k++) {
                    ull ww = bcast2(s_wihA[k*256 + tid]);
                    ulonglong2 u = *(const ulonglong2*)(s_cc + k*8);
                    ulonglong2 v = *(const ulonglong2*)(s_cc + k*8 + 4);
                    FMA2(acc[0], u.x, ww, acc[0]);
                    FMA2(acc[1], u.y, ww, acc[1]);
                    FMA2(acc[2], v.x, ww, acc[2]);
                    FMA2(acc[3], v.y, ww, acc[3]);
                }
            }
            #pragma unroll
            for (int rp = 0; rp < 4; rp++) {
                float2 u = unpack2(acc[rp]);
                s_gt[(2*rp    )*256 + tid] = u.x;
                s_gt[(2*rp + 1)*256 + tid] = u.y;
            }
        }
        __syncthreads();

        // ---- P4: LSTM elementwise for (row r1, local j = jjA, jjA+1) ----
        {
            const float* gr = &s_gt[r1*256];
            float2 ii = *(const float2*)(gr + jjA);
            float2 ff = *(const float2*)(gr + 64 + jjA);
            float2 gv = *(const float2*)(gr + 128 + jjA);
            float2 oo = *(const float2*)(gr + 192 + jjA);
            float i0 = sigm_(ii.x), f0 = sigm_(ff.x), o0 = sigm_(oo.x), g0 = tanh_(gv.x);
            float i1 = sigm_(ii.y), f1 = sigm_(ff.y), o1 = sigm_(oo.y), g1 = tanh_(gv.y);
            cA = f0*cA + i0*g0;  hA = o0 * tanh_(cA);
            cB = f1*cB + i1*g1;  hB = o1 * tanh_(cB);
        }
        // s_hdA double-buffered (par); s_hdB/s_xcB/s_cc/s_gt rewrites are
        // separated by >=1 cluster sync from their last reads.
    }
}

// ---------------- K5: finalize loss -------------------------------------------------
__global__ void k_fin(float* __restrict__ out, int out_size)
{
    int t = threadIdx.x;
    float v = g_num[t] / (g_den[t] + 1e-5f);
    #pragma unroll
    for (int off = 16; off > 0; off >>= 1)
        v += __shfl_down_sync(0xffffffffu, v, off);
    __shared__ float red[8];
    if ((t & 31) == 0) red[t >> 5] = v;
    __syncthreads();
    if (t == 0) {
        float s = 0.f;
        #pragma unroll
        for (int i = 0; i < 8; i++) s += red[i];
        if (out_size > B_*L_*D_) out[B_*L_*D_] = s;
    }
}

// ---------------- launch -------------------------------------------------------------
extern "C" void kernel_launch(void* const* d_in, const int* in_sizes, int n_in,
                              void* d_out, int out_size)
{
    const float* values = (const float*)d_in[0];
    const float* masks  = (const float*)d_in[1];
    const float* deltas = (const float*)d_in[2];
    const float* evalm  = (const float*)d_in[3];
    const float* td_h_W = (const float*)d_in[4];
    const float* td_h_b = (const float*)d_in[5];
    const float* td_x_w = (const float*)d_in[6];
    const float* td_x_b = (const float*)d_in[7];
    const float* hist_W = (const float*)d_in[8];
    const float* hist_b = (const float*)d_in[9];
    const float* feat_W = (const float*)d_in[10];
    const float* feat_b = (const float*)d_in[11];
    const float* wc_W   = (const float*)d_in[12];
    const float* wc_b   = (const float*)d_in[13];
    const float* W_ih   = (const float*)d_in[14];
    const float* W_hh   = (const float*)d_in[15];
    const float* b_ih   = (const float*)d_in[16];
    const float* b_hh   = (const float*)d_in[17];
    float* out = (float*)d_out;

    cudaFuncSetAttribute(k_main4, cudaFuncAttributeMaxDynamicSharedMemorySize, SMEM_BYTES);

    k_prep   <<<256, 256>>>(W_ih, W_hh, td_h_W, wc_W, b_ih, b_hh);
    k_den    <<<L_, 128>>>(evalm);
    k_gamma_h<<<BL_/16, 256>>>(deltas, td_h_b);
    k_alpha  <<<BL_/16, 128>>>(deltas, masks, td_x_w, td_x_b, wc_b);
    k_gpre   <<<BL_/16, 512>>>(masks);
    k_main4  <<<128, 256, SMEM_BYTES>>>(values, masks, evalm, hist_W, feat_W,
                                        hist_b, feat_b, out);
    k_fin    <<<1, 256>>>(out, out_size);
}

// round 10
// speedup vs baseline: 1.5606x; 1.0117x over previous
#include <cuda_runtime.h>
#include <math.h>
#include <stdint.h>

#define B_  256
#define L_  256
#define D_  128
#define H_  256
#define G4_ 1024
#define BL_ (B_*L_)
#define KC_ 384                      // combined k: 256 (Whh) + 128 (WihA)

typedef unsigned long long ull;

// ---------------- f32x2 helpers ---------------------------------------------------
#define FMA2(d,a,b,c) asm("fma.rn.f32x2 %0, %1, %2, %3;" : "=l"(d) : "l"(a), "l"(b), "l"(c))
__device__ __forceinline__ ull bcast2(float v){ ull d; asm("mov.b64 %0, {%1, %1};" : "=l"(d) : "f"(v)); return d; }
__device__ __forceinline__ ull pack2(float lo, float hi){ ull d; asm("mov.b64 %0, {%1, %2};" : "=l"(d) : "f"(lo), "f"(hi)); return d; }
__device__ __forceinline__ float2 unpack2(ull d){ float lo,hi; asm("mov.b64 {%0, %1}, %2;" : "=f"(lo), "=f"(hi) : "l"(d)); return make_float2(lo,hi); }

// ---------------- device scratch (static; no allocations anywhere) ----------------
__device__ float g_gamma_h[BL_*H_];            // 64 MB
__device__ float g_alpha  [BL_*D_];            // 32 MB
// cluster-grouped: [bg(32)][t(256)][q(4)][r(8)][nn(256)]
__device__ float g_gpre   [(size_t)BL_*G4_];   // 256 MB
// combined weights, per-CTA-contiguous: [q(4)][k(384)][nn(256)]
// k<256: Whh[permN(q*256+nn)][k] ; k>=256: WihA = W_ih[permN(q*256+nn)][k-256]
__device__ float g_Wcomb  [4*KC_*256];
__device__ float g_WihB_t [D_*G4_];            // [k][n'] permuted (for k_gpre)
__device__ float g_tdh_t  [D_*H_];             // [d][j]
__device__ float g_wc_t   [(2*D_)*D_];         // [k][dn]
__device__ float g_bias   [G4_];               // permuted b_ih+b_hh
__device__ float g_num    [L_];
__device__ float g_den    [L_];

// gate-column permutation: n' = q*256 + g*64 + jj  <->  n = g*256 + q*64 + jj
__device__ __forceinline__ int permN(int np) {
    return ((np >> 6) & 3) * 256 + (np >> 8) * 64 + (np & 63);
}

// ---------------- K0: weight transposes (permuted) + zero g_num -------------------
__global__ void k_prep(const float* __restrict__ W_ih,   const float* __restrict__ W_hh,
                       const float* __restrict__ td_h_W, const float* __restrict__ wc_W,
                       const float* __restrict__ b_ih,   const float* __restrict__ b_hh)
{
    int idx = blockIdx.x * blockDim.x + threadIdx.x;
    int stride = gridDim.x * blockDim.x;
    for (int i = idx; i < 4*KC_*256; i += stride) {
        int q = i / (KC_*256);
        int rem = i % (KC_*256);
        int k = rem >> 8, nn = rem & 255;
        int n = permN(q*256 + nn);
        g_Wcomb[i] = (k < 256) ? W_hh[n*H_ + k] : W_ih[n*(2*D_) + (k - 256)];
    }
    for (int i = idx; i < D_*G4_; i += stride) {
        int k = i >> 10, np = i & 1023;
        int n = permN(np);
        g_WihB_t[i] = W_ih[n*(2*D_) + D_ + k];
    }
    for (int i = idx; i < D_*H_; i += stride) {
        int d = i / H_, j = i % H_;
        g_tdh_t[i] = td_h_W[j*D_ + d];
    }
    for (int i = idx; i < (2*D_)*D_; i += stride) {
        int k = i / D_, dn = i % D_;
        g_wc_t[i] = wc_W[dn*(2*D_) + k];
    }
    for (int i = idx; i < G4_; i += stride) {
        int n = permN(i);
        g_bias[i] = b_ih[n] + b_hh[n];
    }
    for (int i = idx; i < L_;  i += stride) g_num[i] = 0.f;
}

// ---------------- K0b: per-timestep loss denominator ------------------------------
__global__ void k_den(const float* __restrict__ evalm)
{
    int t = blockIdx.x;
    int tid = threadIdx.x;
    float s = 0.f;
    for (int b = 0; b < B_; b++)
        s += evalm[((size_t)b*L_ + t)*D_ + tid];
    #pragma unroll
    for (int off = 16; off > 0; off >>= 1)
        s += __shfl_down_sync(0xffffffffu, s, off);
    __shared__ float red[4];
    if ((tid & 31) == 0) red[tid >> 5] = s;
    __syncthreads();
    if (tid == 0) g_den[t] = red[0] + red[1] + red[2] + red[3];
}

// ---------------- K1: gamma_h precompute -------------------------------------------
__global__ void __launch_bounds__(256) k_gamma_h(const float* __restrict__ deltas,
                                                 const float* __restrict__ td_h_b)
{
    __shared__ float sd[16][D_];
    int bl0 = blockIdx.x * 16;
    int tid = threadIdx.x;
    #pragma unroll
    for (int i = 0; i < 8; i++) {
        int idx = tid + i*256;
        int r = idx >> 7, d = idx & 127;
        sd[r][d] = deltas[(size_t)(bl0 + r)*D_ + d];
    }
    __syncthreads();
    int j = tid;
    float acc[16];
    float b = td_h_b[j];
    #pragma unroll
    for (int r = 0; r < 16; r++) acc[r] = b;
    #pragma unroll 4
    for (int d = 0; d < D_; d++) {
        float w = g_tdh_t[d*H_ + j];
        #pragma unroll
        for (int r = 0; r < 16; r++) acc[r] += sd[r][d] * w;
    }
    #pragma unroll
    for (int r = 0; r < 16; r++)
        g_gamma_h[(size_t)(bl0 + r)*H_ + j] = __expf(-fmaxf(acc[r], 0.f));
}

// ---------------- K2: alpha precompute ---------------------------------------------
__global__ void __launch_bounds__(128) k_alpha(const float* __restrict__ deltas,
                                               const float* __restrict__ masks,
                                               const float* __restrict__ td_x_w,
                                               const float* __restrict__ td_x_b,
                                               const float* __restrict__ wc_b)
{
    __shared__ float sin_[16][2*D_];
    int bl0 = blockIdx.x * 16;
    int tid = threadIdx.x;
    #pragma unroll
    for (int i = 0; i < 32; i++) {
        int idx = tid + i*128;
        int r = idx >> 8, k = idx & 255;
        float v;
        if (k < D_) {
            float dd = deltas[(size_t)(bl0 + r)*D_ + k];
            v = __expf(-fmaxf(dd*td_x_w[k] + td_x_b[k], 0.f));
        } else {
            v = masks[(size_t)(bl0 + r)*D_ + (k - D_)];
        }
        sin_[r][k] = v;
    }
    __syncthreads();
    int dn = tid;
    float acc[16];
    float b = wc_b[dn];
    #pragma unroll
    for (int r = 0; r < 16; r++) acc[r] = b;
    #pragma unroll 4
    for (int k = 0; k < 2*D_; k++) {
        float w = g_wc_t[k*D_ + dn];
        #pragma unroll
        for (int r = 0; r < 16; r++) acc[r] += sin_[r][k] * w;
    }
    #pragma unroll
    for (int r = 0; r < 16; r++)
        g_alpha[(size_t)(bl0 + r)*D_ + dn] = acc[r];
}

// ---------------- K3: gates m-half precompute (16 rows/CTA) -------------------------
__global__ void __launch_bounds__(512) k_gpre(const float* __restrict__ masks)
{
    __shared__ float sm[D_*16];     // [d][row16]
    int bl0 = blockIdx.x * 16;
    int tid = threadIdx.x;
    #pragma unroll
    for (int i = 0; i < 4; i++) {
        int idx = tid + i*512;
        int r = idx >> 7, d = idx & 127;
        sm[d*16 + r] = masks[(size_t)(bl0 + r)*D_ + d];
    }
    __syncthreads();
    int n2 = tid * 2;
    float2 b2 = *(const float2*)&g_bias[n2];
    ull acc[8][2];
    #pragma unroll
    for (int rp = 0; rp < 8; rp++) { acc[rp][0] = bcast2(b2.x); acc[rp][1] = bcast2(b2.y); }
    #pragma unroll 2
    for (int k = 0; k < D_; k++) {
        float2 w = *(const float2*)&g_WihB_t[k*G4_ + n2];
        ull pw0 = bcast2(w.x), pw1 = bcast2(w.y);
        const ulonglong2* mrow = (const ulonglong2*)&sm[k*16];
        ulonglong2 m0 = mrow[0], m1 = mrow[1], m2 = mrow[2], m3 = mrow[3];
        FMA2(acc[0][0], m0.x, pw0, acc[0][0]); FMA2(acc[0][1], m0.x, pw1, acc[0][1]);
        FMA2(acc[1][0], m0.y, pw0, acc[1][0]); FMA2(acc[1][1], m0.y, pw1, acc[1][1]);
        FMA2(acc[2][0], m1.x, pw0, acc[2][0]); FMA2(acc[2][1], m1.x, pw1, acc[2][1]);
        FMA2(acc[3][0], m1.y, pw0, acc[3][0]); FMA2(acc[3][1], m1.y, pw1, acc[3][1]);
        FMA2(acc[4][0], m2.x, pw0, acc[4][0]); FMA2(acc[4][1], m2.x, pw1, acc[4][1]);
        FMA2(acc[5][0], m2.y, pw0, acc[5][0]); FMA2(acc[5][1], m2.y, pw1, acc[5][1]);
        FMA2(acc[6][0], m3.x, pw0, acc[6][0]); FMA2(acc[6][1], m3.x, pw1, acc[6][1]);
        FMA2(acc[7][0], m3.y, pw0, acc[7][0]); FMA2(acc[7][1], m3.y, pw1, acc[7][1]);
    }
    int b = bl0 >> 8, t0c = bl0 & 255;
    int bg = b >> 3, rr = b & 7;
    int q = n2 >> 8, nn = n2 & 255;
    #pragma unroll
    for (int rp = 0; rp < 8; rp++) {
        float2 u0 = unpack2(acc[rp][0]), u1 = unpack2(acc[rp][1]);
        float2 lo = make_float2(u0.x, u1.x);
        float2 hi = make_float2(u0.y, u1.y);
        size_t aLo = ((((size_t)bg*256 + t0c + 2*rp    )*4 + q)*8 + rr)*256 + nn;
        size_t aHi = ((((size_t)bg*256 + t0c + 2*rp + 1)*4 + q)*8 + rr)*256 + nn;
        *(float2*)&g_gpre[aLo] = lo;
        *(float2*)&g_gpre[aHi] = hi;
    }
}

// ---------------- DSMEM / cp.async helpers ------------------------------------------
__device__ __forceinline__ uint32_t smem_u32_(const void* p) {
    uint32_t a;
    asm("{ .reg .u64 t; cvta.to.shared.u64 t, %1; cvt.u32.u64 %0, t; }"
        : "=r"(a) : "l"(p));
    return a;
}
__device__ __forceinline__ void st_dsmem(uint32_t addr, float v) {
    asm volatile("st.shared::cluster.f32 [%0], %1;" :: "r"(addr), "f"(v) : "memory");
}
__device__ __forceinline__ void st_dsmem64(uint32_t addr, ull v) {
    asm volatile("st.shared::cluster.b64 [%0], %1;" :: "r"(addr), "l"(v) : "memory");
}
__device__ __forceinline__ void cp16(uint32_t dst, const float* src) {
    asm volatile("cp.async.cg.shared.global [%0], [%1], 16;" :: "r"(dst), "l"(src) : "memory");
}
#define CP_COMMIT() asm volatile("cp.async.commit_group;" ::: "memory")
#define CP_WAIT6()  asm volatile("cp.async.wait_group 6;" ::: "memory")
#define CLUSTER_SYNC_() do { \
    asm volatile("barrier.cluster.arrive.aligned;" ::: "memory"); \
    asm volatile("barrier.cluster.wait.aligned;"  ::: "memory"); } while (0)

// SMEM layout (floats)
#define HIST_STRIDE 260
#define FEAT_STRIDE 132
#define SOFF_WS    0                                     // ring: 8 slots x 16k x 256 = 32768
#define SOFF_HISTT (SOFF_WS + 8*4096)                    // 32768
#define SOFF_FEATT (SOFF_HISTT + 32*HIST_STRIDE)         // 41088
#define SOFF_HDA   (SOFF_FEATT + 32*FEAT_STRIDE)         // 45312
#define SOFF_HDB   (SOFF_HDA + 2*256*8)                  // 49408
#define SOFF_XCB   (SOFF_HDB + 8*256)                    // 51456
#define SOFF_CC    (SOFF_XCB + 8*128)                    // 52480
#define SOFF_GT    (SOFF_CC + 128*8)                     // 53504
#define SOFF_NUM   (SOFF_GT + 8*256)                     // 55552
#define SMEM_FLOATS (SOFF_NUM + 16)
#define SMEM_BYTES (SMEM_FLOATS * 4)

__device__ __forceinline__ float sigm_(float x) { return 1.f / (1.f + __expf(-x)); }
__device__ __forceinline__ float tanh_(float x) { return 2.f / (1.f + __expf(-2.f*x)) - 1.f; }

// ---------------- K4: cluster-4 recurrence, SMEM-staged weight ring -----------------
__global__ void __launch_bounds__(256) __cluster_dims__(4, 1, 1)
k_main4(const float* __restrict__ values, const float* __restrict__ masks,
        const float* __restrict__ evalm,
        const float* __restrict__ hist_W, const float* __restrict__ feat_W,
        const float* __restrict__ hist_b, const float* __restrict__ feat_b,
        float* __restrict__ out)
{
    extern __shared__ float smf[];
    float* s_ws    = smf + SOFF_WS;      // [8][16*256] weight ring
    float* s_histT = smf + SOFF_HISTT;   // [32][260]
    float* s_featT = smf + SOFF_FEATT;   // [32][132]
    float* s_hdA   = smf + SOFF_HDA;     // [2][256][8]
    float* s_hdB   = smf + SOFF_HDB;     // [8][256]
    float* s_xcB   = smf + SOFF_XCB;     // [8][128]
    float* s_cc    = smf + SOFF_CC;      // [128][8]
    float* s_gt    = smf + SOFF_GT;      // [8][256]
    float* s_num   = smf + SOFF_NUM;

    const int tid = threadIdx.x;
    uint32_t q;
    asm("mov.u32 %0, %%cluster_ctarank;" : "=r"(q));
    const int bg = blockIdx.x >> 2;
    const int b0 = bg * 8;

    // --- preload stationary hist/feat slices ---
    #pragma unroll 4
    for (int i = tid; i < 32*256; i += 256) {
        int dd = i >> 8, k = i & 255;
        s_histT[dd*HIST_STRIDE + k] = hist_W[((int)q*32 + dd)*H_ + k];
    }
    #pragma unroll 2
    for (int i = tid; i < 32*128; i += 256) {
        int dd = i >> 7, k = i & 127;
        int dgx = (int)q*32 + dd;
        s_featT[dd*FEAT_STRIDE + k] = (k == dgx) ? 0.f : feat_W[dgx*D_ + k];
    }
    if (tid == 0) s_num[0] = 0.f;
    __syncthreads();

    // remote SMEM bases for the 4 ranks
    uint32_t sbase = smem_u32_(smf);
    uint32_t rb0, rb1, rb2, rb3;
    asm("mapa.shared::cluster.u32 %0, %1, %2;" : "=r"(rb0) : "r"(sbase), "r"(0u));
    asm("mapa.shared::cluster.u32 %0, %1, %2;" : "=r"(rb1) : "r"(sbase), "r"(1u));
    asm("mapa.shared::cluster.u32 %0, %1, %2;" : "=r"(rb2) : "r"(sbase), "r"(2u));
    asm("mapa.shared::cluster.u32 %0, %1, %2;" : "=r"(rb3) : "r"(sbase), "r"(3u));

    // thread mappings
    const int r1 = tid >> 5;                 // batch row 0..7 (one per warp)
    const int dd = tid & 31;                 // within-slice d
    const int dg = (int)q*32 + dd;           // global d
    const int jjA = dd*2;                    // two owned (local) h-indices
    const int jgA = (int)q*64 + jjA;         // global h index
    const float hb = hist_b[dg], fb = feat_b[dg];

    const size_t ib0   = ((size_t)(b0+r1)*L_)*D_ + dg;    // + t*D_
    const size_t gam0  = ((size_t)(b0+r1)*L_)*H_ + jgA;   // + t*H_
    const float* gWq   = g_Wcomb + (size_t)q*KC_*256;     // combined weight slice
    const float* gp0   = g_gpre + (((size_t)bg*256*4 + q)*8)*256 + tid;  // + t*4*8*256

    // weight-ring prefetch: chunk m (0..23) -> slot sl; 4 x 16B per thread
    const uint32_t ws_b = sbase + (uint32_t)SOFF_WS*4u + (uint32_t)tid*16u;
    #define PREFETCH_CHUNK(m, sl) do { \
        const float* _src = gWq + (m)*4096 + tid*4; \
        uint32_t _dst = ws_b + (uint32_t)(sl)*16384u; \
        cp16(_dst,           _src); \
        cp16(_dst +  4096u,  _src + 1024); \
        cp16(_dst +  8192u,  _src + 2048); \
        cp16(_dst + 12288u,  _src + 3072); \
        CP_COMMIT(); \
    } while (0)

    // warmup: chunks 0..5 in flight
    #pragma unroll
    for (int a = 0; a < 6; a++) PREFETCH_CHUNK(a, a);

    float hA = 0.f, hB = 0.f, cA = 0.f, cB = 0.f;

    // rotated prefetch registers (step 0)
    float2 gg   = __ldcs((const float2*)&g_gamma_h[gam0]);
    float  xv_n = __ldcs(&values[ib0]);
    float  mv_n = __ldcs(&masks[ib0]);
    float  al_n = __ldcs(&g_alpha[ib0]);
    float  ev_n = __ldcs(&evalm[ib0]);

    for (int t = 0; t < L_; t++) {
        const int par = t & 1;
        const int tn = (t + 1) & 255;         // wrapped (last iter value unused)

        // ---- gpre prefetch for THIS step (consumed in P3) ----
        float g8[8];
        {
            const float* gp = gp0 + (size_t)t*(4*8*256);
            #pragma unroll
            for (int r = 0; r < 8; r++) g8[r] = __ldcs(gp + r*256);
        }

        // ---- P0: decay h, push hd (layouts A [k][row] and B [row][k]) ----
        {
            float hdA = hA * gg.x;
            float hdB = hB * gg.y;
            uint32_t oA = (uint32_t)(SOFF_HDA + ((par*256 + jgA)*8 + r1)) * 4u;
            uint32_t oA2 = oA + 32u;
            ull hp = pack2(hdA, hdB);
            uint32_t oB = (uint32_t)(SOFF_HDB + (r1*256 + jgA)) * 4u;
            st_dsmem(rb0 + oA, hdA); st_dsmem(rb0 + oA2, hdB); st_dsmem64(rb0 + oB, hp);
            st_dsmem(rb1 + oA, hdA); st_dsmem(rb1 + oA2, hdB); st_dsmem64(rb1 + oB, hp);
            st_dsmem(rb2 + oA, hdA); st_dsmem(rb2 + oA2, hdB); st_dsmem64(rb2 + oB, hp);
            st_dsmem(rb3 + oA, hdA); st_dsmem(rb3 + oA2, hdB); st_dsmem64(rb3 + oB, hp);
            gg = __ldcs((const float2*)&g_gamma_h[gam0 + (size_t)tn*H_]);
        }
        CLUSTER_SYNC_();

        // ---- P1: x_h = hd . hist_row(dg) ; xc ; push xc ----
        const size_t ib = ib0 + (size_t)t*D_;
        const float xv = xv_n;
        const float mv = mv_n;
        {
            const size_t ibn = ib0 + (size_t)tn*D_;
            xv_n = __ldcs(&values[ibn]);
            mv_n = __ldcs(&masks[ibn]);
        }
        float xh;
        {
            const float* hp = &s_hdB[r1*256];
            const float* wpt = &s_histT[dd*HIST_STRIDE];
            ull a0 = 0, a1 = 0, a2 = 0, a3 = 0;
            #pragma unroll 8
            for (int k = 0; k < 256; k += 8) {
                ulonglong2 hv  = *(const ulonglong2*)(hp + k);
                ulonglong2 hv2 = *(const ulonglong2*)(hp + k + 4);
                ulonglong2 wv  = *(const ulonglong2*)(wpt + k);
                ulonglong2 wv2 = *(const ulonglong2*)(wpt + k + 4);
                FMA2(a0, hv.x,  wv.x,  a0);
                FMA2(a1, hv.y,  wv.y,  a1);
                FMA2(a2, hv2.x, wv2.x, a2);
                FMA2(a3, hv2.y, wv2.y, a3);
            }
            float2 p0 = unpack2(a0), p1 = unpack2(a1), p2 = unpack2(a2), p3 = unpack2(a3);
            xh = hb + ((p0.x + p0.y) + (p1.x + p1.y)) + ((p2.x + p2.y) + (p3.x + p3.y));
        }
        const float xc = mv*xv + (1.f - mv)*xh;
        {
            uint32_t o = (uint32_t)(SOFF_XCB + (r1*128 + dg)) * 4u;
            st_dsmem(rb0 + o, xc); st_dsmem(rb1 + o, xc);
            st_dsmem(rb2 + o, xc); st_dsmem(rb3 + o, xc);
        }
        CLUSTER_SYNC_();

        // ---- P2: z_h, c_h, c_c, imputation out, loss; push cc ----
        float cc;
        {
            const float al = al_n;
            const float me = ev_n;
            {
                const size_t ibn = ib0 + (size_t)tn*D_;
                al_n = __ldcs(&g_alpha[ibn]);
                ev_n = __ldcs(&evalm[ibn]);
            }
            const float* xp = &s_xcB[r1*128];
            const float* wpt = &s_featT[dd*FEAT_STRIDE];
            ull a0 = 0, a1 = 0;
            #pragma unroll 8
            for (int k = 0; k < 128; k += 4) {
                ulonglong2 xv2 = *(const ulonglong2*)(xp + k);
                ulonglong2 wv2 = *(const ulonglong2*)(wpt + k);
                FMA2(a0, xv2.x, wv2.x, a0);
                FMA2(a1, xv2.y, wv2.y, a1);
            }
            float2 p0 = unpack2(a0), p1 = unpack2(a1);
            float zh = fb + (p0.x + p0.y) + (p1.x + p1.y);
            float ch = al*zh + (1.f - al)*xh;
            cc = mv*xv + (1.f - mv)*ch;
            __stcs(&out[ib], cc);
            float p = fabsf(cc - xv) * me;
            #pragma unroll
            for (int off = 16; off > 0; off >>= 1)
                p += __shfl_down_sync(0xffffffffu, p, off);
            if (dd == 0) atomicAdd(s_num, p);
            uint32_t o = (uint32_t)(SOFF_CC + (dg*8 + r1)) * 4u;
            st_dsmem(rb0 + o, cc); st_dsmem(rb1 + o, cc);
            st_dsmem(rb2 + o, cc); st_dsmem(rb3 + o, cc);
        }
        CLUSTER_SYNC_();

        // ---- P3: gates = gpre + [hd|cc] @ Wcomb-slice, staged through SMEM ring ----
        if (tid == 0) {
            atomicAdd(&g_num[t], s_num[0]);
            s_num[0] = 0.f;
        }
        {
            ull acc[4];
            acc[0] = pack2(g8[0], g8[1]); acc[1] = pack2(g8[2], g8[3]);
            acc[2] = pack2(g8[4], g8[5]); acc[3] = pack2(g8[6], g8[7]);
            const float* hdp = &s_hdA[par*2048];
            for (int c = 0; c < 24; c++) {
                int m = c + 6; if (m >= 24) m -= 24;     // prefetch 6 chunks ahead (wraps)
                PREFETCH_CHUNK(m, m & 7);
                CP_WAIT6();                               // chunk c's group complete
                __syncthreads();                          // visible to all warps
                const float* wsrc = &s_ws[(c & 7)*4096];
                const float* msrc = (c < 16) ? (hdp + c*128) : (s_cc + (c - 16)*128);
                #pragma unroll
                for (int kk = 0; kk < 16; kk++) {
                    ull ww = bcast2(wsrc[kk*256 + tid]);
                    ulonglong2 u = *(const ulonglong2*)(msrc + kk*8);
                    ulonglong2 v = *(const ulonglong2*)(msrc + kk*8 + 4);
                    FMA2(acc[0], u.x, ww, acc[0]);
                    FMA2(acc[1], u.y, ww, acc[1]);
                    FMA2(acc[2], v.x, ww, acc[2]);
                    FMA2(acc[3], v.y, ww, acc[3]);
                }
            }
            #pragma unroll
            for (int rp = 0; rp < 4; rp++) {
                float2 u = unpack2(acc[rp]);
                s_gt[(2*rp    )*256 + tid] = u.x;
                s_gt[(2*rp + 1)*256 + tid] = u.y;
            }
        }
        __syncthreads();

        // ---- P4: LSTM elementwise for (row r1, local j = jjA, jjA+1) ----
        {
            const float* gr = &s_gt[r1*256];
            float2 ii = *(const float2*)(gr + jjA);
            float2 ff = *(const float2*)(gr + 64 + jjA);
            float2 gv = *(const float2*)(gr + 128 + jjA);
            float2 oo = *(const float2*)(gr + 192 + jjA);
            float i0 = sigm_(ii.x), f0 = sigm_(ff.x), o0 = sigm_(oo.x), g0 = tanh_(gv.x);
            float i1 = sigm_(ii.y), f1 = sigm_(ff.y), o1 = sigm_(oo.y), g1 = tanh_(gv.y);
            cA = f0*cA + i0*g0;  hA = o0 * tanh_(cA);
            cB = f1*cB + i1*g1;  hB = o1 * tanh_(cB);
        }
        // s_hdA double-buffered (par); s_hdB/s_xcB/s_cc/s_gt rewrites are
        // separated by >=1 cluster sync from their last reads; ring slots are
        // reused only 8 chunks (>=2 barriers) after their last read.
    }
    #undef PREFETCH_CHUNK
}

// ---------------- K5: finalize loss -------------------------------------------------
__global__ void k_fin(float* __restrict__ out, int out_size)
{
    int t = threadIdx.x;
    float v = g_num[t] / (g_den[t] + 1e-5f);
    #pragma unroll
    for (int off = 16; off > 0; off >>= 1)
        v += __shfl_down_sync(0xffffffffu, v, off);
    __shared__ float red[8];
    if ((t & 31) == 0) red[t >> 5] = v;
    __syncthreads();
    if (t == 0) {
        float s = 0.f;
        #pragma unroll
        for (int i = 0; i < 8; i++) s += red[i];
        if (out_size > B_*L_*D_) out[B_*L_*D_] = s;
    }
}

// ---------------- launch -------------------------------------------------------------
extern "C" void kernel_launch(void* const* d_in, const int* in_sizes, int n_in,
                              void* d_out, int out_size)
{
    const float* values = (const float*)d_in[0];
    const float* masks  = (const float*)d_in[1];
    const float* deltas = (const float*)d_in[2];
    const float* evalm  = (const float*)d_in[3];
    const float* td_h_W = (const float*)d_in[4];
    const float* td_h_b = (const float*)d_in[5];
    const float* td_x_w = (const float*)d_in[6];
    const float* td_x_b = (const float*)d_in[7];
    const float* hist_W = (const float*)d_in[8];
    const float* hist_b = (const float*)d_in[9];
    const float* feat_W = (const float*)d_in[10];
    const float* feat_b = (const float*)d_in[11];
    const float* wc_W   = (const float*)d_in[12];
    const float* wc_b   = (const float*)d_in[13];
    const float* W_ih   = (const float*)d_in[14];
    const float* W_hh   = (const float*)d_in[15];
    const float* b_ih   = (const float*)d_in[16];
    const float* b_hh   = (const float*)d_in[17];
    float* out = (float*)d_out;

    cudaFuncSetAttribute(k_main4, cudaFuncAttributeMaxDynamicSharedMemorySize, SMEM_BYTES);

    k_prep   <<<256, 256>>>(W_ih, W_hh, td_h_W, wc_W, b_ih, b_hh);
    k_den    <<<L_, 128>>>(evalm);
    k_gamma_h<<<BL_/16, 256>>>(deltas, td_h_b);
    k_alpha  <<<BL_/16, 128>>>(deltas, masks, td_x_w, td_x_b, wc_b);
    k_gpre   <<<BL_/16, 512>>>(masks);
    k_main4  <<<128, 256, SMEM_BYTES>>>(values, masks, evalm, hist_W, feat_W,
                                        hist_b, feat_b, out);
    k_fin    <<<1, 256>>>(out, out_size);
}

// round 11
// speedup vs baseline: 1.6391x; 1.0503x over previous
#include <cuda_runtime.h>
#include <math.h>
#include <stdint.h>

#define B_  256
#define L_  256
#define D_  128
#define H_  256
#define G4_ 1024
#define BL_ (B_*L_)
#define KC_ 384                      // combined k: 256 (Whh) + 128 (WihA)

typedef unsigned long long ull;

// ---------------- f32x2 helpers ---------------------------------------------------
#define FMA2(d,a,b,c) asm("fma.rn.f32x2 %0, %1, %2, %3;" : "=l"(d) : "l"(a), "l"(b), "l"(c))
__device__ __forceinline__ ull bcast2(float v){ ull d; asm("mov.b64 %0, {%1, %1};" : "=l"(d) : "f"(v)); return d; }
__device__ __forceinline__ ull pack2(float lo, float hi){ ull d; asm("mov.b64 %0, {%1, %2};" : "=l"(d) : "f"(lo), "f"(hi)); return d; }
__device__ __forceinline__ float2 unpack2(ull d){ float lo,hi; asm("mov.b64 {%0, %1}, %2;" : "=f"(lo), "=f"(hi) : "l"(d)); return make_float2(lo,hi); }

// ---------------- device scratch (static; no allocations anywhere) ----------------
__device__ float g_gamma_h[BL_*H_];            // 64 MB
__device__ float g_alpha  [BL_*D_];            // 32 MB
// cluster-grouped: [bg(32)][t(256)][q(4)][r(8)][nn(256)]
__device__ float g_gpre   [(size_t)BL_*G4_];   // 256 MB
// combined weights, per-CTA-contiguous: [q(4)][k(384)][nn(256)]
__device__ float g_Wcomb  [4*KC_*256];
__device__ float g_WihB_t [D_*G4_];            // [k][n'] permuted (for k_gpre)
__device__ float g_tdh_t  [D_*H_];             // [d][j]
__device__ float g_wc_t   [(2*D_)*D_];         // [k][dn]
__device__ float g_bias   [G4_];               // permuted b_ih+b_hh
__device__ float g_num    [L_];
__device__ float g_den    [L_];

// gate-column permutation: n' = q*256 + g*64 + jj  <->  n = g*256 + q*64 + jj
__device__ __forceinline__ int permN(int np) {
    return ((np >> 6) & 3) * 256 + (np >> 8) * 64 + (np & 63);
}

// ---------------- K0: weight transposes (permuted) + zero g_num -------------------
__global__ void k_prep(const float* __restrict__ W_ih,   const float* __restrict__ W_hh,
                       const float* __restrict__ td_h_W, const float* __restrict__ wc_W,
                       const float* __restrict__ b_ih,   const float* __restrict__ b_hh)
{
    int idx = blockIdx.x * blockDim.x + threadIdx.x;
    int stride = gridDim.x * blockDim.x;
    for (int i = idx; i < 4*KC_*256; i += stride) {
        int q = i / (KC_*256);
        int rem = i % (KC_*256);
        int k = rem >> 8, nn = rem & 255;
        int n = permN(q*256 + nn);
        g_Wcomb[i] = (k < 256) ? W_hh[n*H_ + k] : W_ih[n*(2*D_) + (k - 256)];
    }
    for (int i = idx; i < D_*G4_; i += stride) {
        int k = i >> 10, np = i & 1023;
        int n = permN(np);
        g_WihB_t[i] = W_ih[n*(2*D_) + D_ + k];
    }
    for (int i = idx; i < D_*H_; i += stride) {
        int d = i / H_, j = i % H_;
        g_tdh_t[i] = td_h_W[j*D_ + d];
    }
    for (int i = idx; i < (2*D_)*D_; i += stride) {
        int k = i / D_, dn = i % D_;
        g_wc_t[i] = wc_W[dn*(2*D_) + k];
    }
    for (int i = idx; i < G4_; i += stride) {
        int n = permN(i);
        g_bias[i] = b_ih[n] + b_hh[n];
    }
    for (int i = idx; i < L_;  i += stride) g_num[i] = 0.f;
}

// ---------------- K0b: per-timestep loss denominator ------------------------------
__global__ void k_den(const float* __restrict__ evalm)
{
    int t = blockIdx.x;
    int tid = threadIdx.x;
    float s = 0.f;
    for (int b = 0; b < B_; b++)
        s += evalm[((size_t)b*L_ + t)*D_ + tid];
    #pragma unroll
    for (int off = 16; off > 0; off >>= 1)
        s += __shfl_down_sync(0xffffffffu, s, off);
    __shared__ float red[4];
    if ((tid & 31) == 0) red[tid >> 5] = s;
    __syncthreads();
    if (tid == 0) g_den[t] = red[0] + red[1] + red[2] + red[3];
}

// ---------------- K1: gamma_h precompute -------------------------------------------
__global__ void __launch_bounds__(256) k_gamma_h(const float* __restrict__ deltas,
                                                 const float* __restrict__ td_h_b)
{
    __shared__ float sd[16][D_];
    int bl0 = blockIdx.x * 16;
    int tid = threadIdx.x;
    #pragma unroll
    for (int i = 0; i < 8; i++) {
        int idx = tid + i*256;
        int r = idx >> 7, d = idx & 127;
        sd[r][d] = deltas[(size_t)(bl0 + r)*D_ + d];
    }
    __syncthreads();
    int j = tid;
    float acc[16];
    float b = td_h_b[j];
    #pragma unroll
    for (int r = 0; r < 16; r++) acc[r] = b;
    #pragma unroll 4
    for (int d = 0; d < D_; d++) {
        float w = g_tdh_t[d*H_ + j];
        #pragma unroll
        for (int r = 0; r < 16; r++) acc[r] += sd[r][d] * w;
    }
    #pragma unroll
    for (int r = 0; r < 16; r++)
        g_gamma_h[(size_t)(bl0 + r)*H_ + j] = __expf(-fmaxf(acc[r], 0.f));
}

// ---------------- K2: alpha precompute ---------------------------------------------
__global__ void __launch_bounds__(128) k_alpha(const float* __restrict__ deltas,
                                               const float* __restrict__ masks,
                                               const float* __restrict__ td_x_w,
                                               const float* __restrict__ td_x_b,
                                               const float* __restrict__ wc_b)
{
    __shared__ float sin_[16][2*D_];
    int bl0 = blockIdx.x * 16;
    int tid = threadIdx.x;
    #pragma unroll
    for (int i = 0; i < 32; i++) {
        int idx = tid + i*128;
        int r = idx >> 8, k = idx & 255;
        float v;
        if (k < D_) {
            float dd = deltas[(size_t)(bl0 + r)*D_ + k];
            v = __expf(-fmaxf(dd*td_x_w[k] + td_x_b[k], 0.f));
        } else {
            v = masks[(size_t)(bl0 + r)*D_ + (k - D_)];
        }
        sin_[r][k] = v;
    }
    __syncthreads();
    int dn = tid;
    float acc[16];
    float b = wc_b[dn];
    #pragma unroll
    for (int r = 0; r < 16; r++) acc[r] = b;
    #pragma unroll 4
    for (int k = 0; k < 2*D_; k++) {
        float w = g_wc_t[k*D_ + dn];
        #pragma unroll
        for (int r = 0; r < 16; r++) acc[r] += sin_[r][k] * w;
    }
    #pragma unroll
    for (int r = 0; r < 16; r++)
        g_alpha[(size_t)(bl0 + r)*D_ + dn] = acc[r];
}

// ---------------- K3: gates m-half precompute (16 rows/CTA) -------------------------
__global__ void __launch_bounds__(512) k_gpre(const float* __restrict__ masks)
{
    __shared__ float sm[D_*16];     // [d][row16]
    int bl0 = blockIdx.x * 16;
    int tid = threadIdx.x;
    #pragma unroll
    for (int i = 0; i < 4; i++) {
        int idx = tid + i*512;
        int r = idx >> 7, d = idx & 127;
        sm[d*16 + r] = masks[(size_t)(bl0 + r)*D_ + d];
    }
    __syncthreads();
    int n2 = tid * 2;
    float2 b2 = *(const float2*)&g_bias[n2];
    ull acc[8][2];
    #pragma unroll
    for (int rp = 0; rp < 8; rp++) { acc[rp][0] = bcast2(b2.x); acc[rp][1] = bcast2(b2.y); }
    #pragma unroll 2
    for (int k = 0; k < D_; k++) {
        float2 w = *(const float2*)&g_WihB_t[k*G4_ + n2];
        ull pw0 = bcast2(w.x), pw1 = bcast2(w.y);
        const ulonglong2* mrow = (const ulonglong2*)&sm[k*16];
        ulonglong2 m0 = mrow[0], m1 = mrow[1], m2 = mrow[2], m3 = mrow[3];
        FMA2(acc[0][0], m0.x, pw0, acc[0][0]); FMA2(acc[0][1], m0.x, pw1, acc[0][1]);
        FMA2(acc[1][0], m0.y, pw0, acc[1][0]); FMA2(acc[1][1], m0.y, pw1, acc[1][1]);
        FMA2(acc[2][0], m1.x, pw0, acc[2][0]); FMA2(acc[2][1], m1.x, pw1, acc[2][1]);
        FMA2(acc[3][0], m1.y, pw0, acc[3][0]); FMA2(acc[3][1], m1.y, pw1, acc[3][1]);
        FMA2(acc[4][0], m2.x, pw0, acc[4][0]); FMA2(acc[4][1], m2.x, pw1, acc[4][1]);
        FMA2(acc[5][0], m2.y, pw0, acc[5][0]); FMA2(acc[5][1], m2.y, pw1, acc[5][1]);
        FMA2(acc[6][0], m3.x, pw0, acc[6][0]); FMA2(acc[6][1], m3.x, pw1, acc[6][1]);
        FMA2(acc[7][0], m3.y, pw0, acc[7][0]); FMA2(acc[7][1], m3.y, pw1, acc[7][1]);
    }
    int b = bl0 >> 8, t0c = bl0 & 255;
    int bg = b >> 3, rr = b & 7;
    int q = n2 >> 8, nn = n2 & 255;
    #pragma unroll
    for (int rp = 0; rp < 8; rp++) {
        float2 u0 = unpack2(acc[rp][0]), u1 = unpack2(acc[rp][1]);
        float2 lo = make_float2(u0.x, u1.x);
        float2 hi = make_float2(u0.y, u1.y);
        size_t aLo = ((((size_t)bg*256 + t0c + 2*rp    )*4 + q)*8 + rr)*256 + nn;
        size_t aHi = ((((size_t)bg*256 + t0c + 2*rp + 1)*4 + q)*8 + rr)*256 + nn;
        *(float2*)&g_gpre[aLo] = lo;
        *(float2*)&g_gpre[aHi] = hi;
    }
}

// ---------------- DSMEM helpers -----------------------------------------------------
__device__ __forceinline__ uint32_t smem_u32_(const void* p) {
    uint32_t a;
    asm("{ .reg .u64 t; cvta.to.shared.u64 t, %1; cvt.u32.u64 %0, t; }"
        : "=r"(a) : "l"(p));
    return a;
}
__device__ __forceinline__ void st_dsmem(uint32_t addr, float v) {
    asm volatile("st.shared::cluster.f32 [%0], %1;" :: "r"(addr), "f"(v) : "memory");
}
__device__ __forceinline__ void st_dsmem64(uint32_t addr, ull v) {
    asm volatile("st.shared::cluster.b64 [%0], %1;" :: "r"(addr), "l"(v) : "memory");
}
#define CLUSTER_SYNC_() do { \
    asm volatile("barrier.cluster.arrive.aligned;" ::: "memory"); \
    asm volatile("barrier.cluster.wait.aligned;"  ::: "memory"); } while (0)

// SMEM layout (floats)
#define HIST_STRIDE 260
#define FEAT_STRIDE 132
#define SOFF_HISTT 0                                     // 32*260 = 8320
#define SOFF_FEATT (SOFF_HISTT + 32*HIST_STRIDE)         // 8320
#define SOFF_HDA   (SOFF_FEATT + 32*FEAT_STRIDE)         // 12544
#define SOFF_HDB   (SOFF_HDA + 2*256*8)                  // 16640
#define SOFF_XCB   (SOFF_HDB + 8*256)                    // 18688
#define SOFF_CC    (SOFF_XCB + 8*128)                    // 19712
#define SOFF_GT    (SOFF_CC + 128*8)                     // 20736
#define SOFF_RED   (SOFF_GT + 8*256)                     // 22784  [8][256] scratch
#define SOFF_NUM   (SOFF_RED + 8*256)                    // 24832
#define SMEM_FLOATS (SOFF_NUM + 16)
#define SMEM_BYTES (SMEM_FLOATS * 4)

__device__ __forceinline__ float sigm_(float x) { return 1.f / (1.f + __expf(-x)); }
__device__ __forceinline__ float tanh_(float x) { return 2.f / (1.f + __expf(-2.f*x)) - 1.f; }

// ---------------- K4: cluster-4 recurrence, 512 threads, k-split halves -------------
__global__ void __launch_bounds__(512) __cluster_dims__(4, 1, 1)
k_main4(const float* __restrict__ values, const float* __restrict__ masks,
        const float* __restrict__ evalm,
        const float* __restrict__ hist_W, const float* __restrict__ feat_W,
        const float* __restrict__ hist_b, const float* __restrict__ feat_b,
        float* __restrict__ out)
{
    extern __shared__ float smf[];
    float* s_histT = smf + SOFF_HISTT;   // [32][260]
    float* s_featT = smf + SOFF_FEATT;   // [32][132]
    float* s_hdA   = smf + SOFF_HDA;     // [2][256][8]
    float* s_hdB   = smf + SOFF_HDB;     // [8][256]
    float* s_xcB   = smf + SOFF_XCB;     // [8][128]
    float* s_cc    = smf + SOFF_CC;      // [128][8]
    float* s_gt    = smf + SOFF_GT;      // [8][256]
    float* s_red   = smf + SOFF_RED;     // [8][256] reduction scratch
    float* s_num   = smf + SOFF_NUM;

    const int tid = threadIdx.x;
    const int id  = tid & 255;           // phase-local index
    const int w2  = tid >> 8;            // k-half 0/1
    uint32_t q;
    asm("mov.u32 %0, %%cluster_ctarank;" : "=r"(q));
    const int bg = blockIdx.x >> 2;
    const int b0 = bg * 8;

    // --- preload stationary hist/feat slices ---
    #pragma unroll 4
    for (int i = tid; i < 32*256; i += 512) {
        int dd = i >> 8, k = i & 255;
        s_histT[dd*HIST_STRIDE + k] = hist_W[((int)q*32 + dd)*H_ + k];
    }
    #pragma unroll 2
    for (int i = tid; i < 32*128; i += 512) {
        int dd = i >> 7, k = i & 127;
        int dgx = (int)q*32 + dd;
        s_featT[dd*FEAT_STRIDE + k] = (k == dgx) ? 0.f : feat_W[dgx*D_ + k];
    }
    if (tid == 0) s_num[0] = 0.f;
    __syncthreads();

    // remote SMEM bases: this half pushes to 2 ranks (w2=0 -> 0,1 ; w2=1 -> 2,3)
    uint32_t sbase = smem_u32_(smf);
    uint32_t rbA, rbB;
    asm("mapa.shared::cluster.u32 %0, %1, %2;" : "=r"(rbA) : "r"(sbase), "r"((uint32_t)(2*w2)));
    asm("mapa.shared::cluster.u32 %0, %1, %2;" : "=r"(rbB) : "r"(sbase), "r"((uint32_t)(2*w2 + 1)));

    // thread mappings
    const int r1 = id >> 5;                  // batch row 0..7
    const int dd = id & 31;                  // within-slice d
    const int dg = (int)q*32 + dd;           // global d
    const int jjA = dd*2;                    // two owned (local) h-indices
    const int jgA = (int)q*64 + jjA;         // global h index
    const float hb = hist_b[dg], fb = feat_b[dg];

    const size_t ib0   = ((size_t)(b0+r1)*L_)*D_ + dg;
    const size_t gam0  = ((size_t)(b0+r1)*L_)*H_ + jgA;
    const float* wp    = g_Wcomb + ((size_t)q)*KC_*256 + id;
    const float* gp0   = g_gpre + (((size_t)bg*256*4 + q)*8)*256 + id;

    float hA = 0.f, hB = 0.f, cA = 0.f, cB = 0.f;   // mirrored in both halves

    float2 gg   = __ldcs((const float2*)&g_gamma_h[gam0]);
    float  xv_n = __ldcs(&values[ib0]);
    float  mv_n = __ldcs(&masks[ib0]);
    float  al_n = __ldcs(&g_alpha[ib0]);
    float  ev_n = __ldcs(&evalm[ib0]);

    for (int t = 0; t < L_; t++) {
        const int par = t & 1;
        const int tn = (t + 1) & 255;

        // ---- gpre prefetch (w2==0 only; consumed in P3) ----
        float g8[8];
        if (w2 == 0) {
            const float* gp = gp0 + (size_t)t*(4*8*256);
            #pragma unroll
            for (int r = 0; r < 8; r++) g8[r] = __ldcs(gp + r*256);
        }

        // ---- P0: decay h, push hd to this half's 2 ranks ----
        {
            float hdA = hA * gg.x;
            float hdB = hB * gg.y;
            uint32_t oA = (uint32_t)(SOFF_HDA + ((par*256 + jgA)*8 + r1)) * 4u;
            uint32_t oA2 = oA + 32u;
            ull hp = pack2(hdA, hdB);
            uint32_t oB = (uint32_t)(SOFF_HDB + (r1*256 + jgA)) * 4u;
            st_dsmem(rbA + oA, hdA); st_dsmem(rbA + oA2, hdB); st_dsmem64(rbA + oB, hp);
            st_dsmem(rbB + oA, hdA); st_dsmem(rbB + oA2, hdB); st_dsmem64(rbB + oB, hp);
            gg = __ldcs((const float2*)&g_gamma_h[gam0 + (size_t)tn*H_]);
        }
        CLUSTER_SYNC_();

        // ---- P1: partial x_h over k-half [128*w2, 128*w2+128) ----
        const size_t ib = ib0 + (size_t)t*D_;
        const float xv = xv_n;
        const float mv = mv_n;
        {
            const size_t ibn = ib0 + (size_t)tn*D_;
            xv_n = __ldcs(&values[ibn]);
            mv_n = __ldcs(&masks[ibn]);
        }
        {
            const float* hp = &s_hdB[r1*256 + w2*128];
            const float* wpt = &s_histT[dd*HIST_STRIDE + w2*128];
            ull a0 = 0, a1 = 0, a2 = 0, a3 = 0;
            #pragma unroll 8
            for (int k = 0; k < 128; k += 8) {
                ulonglong2 hv  = *(const ulonglong2*)(hp + k);
                ulonglong2 hv2 = *(const ulonglong2*)(hp + k + 4);
                ulonglong2 wv  = *(const ulonglong2*)(wpt + k);
                ulonglong2 wv2 = *(const ulonglong2*)(wpt + k + 4);
                FMA2(a0, hv.x,  wv.x,  a0);
                FMA2(a1, hv.y,  wv.y,  a1);
                FMA2(a2, hv2.x, wv2.x, a2);
                FMA2(a3, hv2.y, wv2.y, a3);
            }
            float2 p0 = unpack2(a0), p1 = unpack2(a1), p2 = unpack2(a2), p3 = unpack2(a3);
            float part = ((p0.x + p0.y) + (p1.x + p1.y)) + ((p2.x + p2.y) + (p3.x + p3.y));
            if (w2 == 0) part += hb;
            s_red[w2*256 + id] = part;
        }
        __syncthreads();
        const float xh = s_red[id] + s_red[256 + id];
        const float xc = mv*xv + (1.f - mv)*xh;
        {
            uint32_t o = (uint32_t)(SOFF_XCB + (r1*128 + dg)) * 4u;
            st_dsmem(rbA + o, xc); st_dsmem(rbB + o, xc);
        }
        CLUSTER_SYNC_();

        // ---- P2: partial z_h over k-half [64*w2, 64*w2+64) ----
        float cc;
        {
            const float* xp = &s_xcB[r1*128 + w2*64];
            const float* wpt = &s_featT[dd*FEAT_STRIDE + w2*64];
            ull a0 = 0, a1 = 0;
            #pragma unroll 8
            for (int k = 0; k < 64; k += 4) {
                ulonglong2 xv2 = *(const ulonglong2*)(xp + k);
                ulonglong2 wv2 = *(const ulonglong2*)(wpt + k);
                FMA2(a0, xv2.x, wv2.x, a0);
                FMA2(a1, xv2.y, wv2.y, a1);
            }
            float2 p0 = unpack2(a0), p1 = unpack2(a1);
            float part = (p0.x + p0.y) + (p1.x + p1.y);
            if (w2 == 0) part += fb;
            s_red[w2*256 + id] = part;
        }
        __syncthreads();
        {
            const float zh = s_red[id] + s_red[256 + id];
            const float al = al_n;
            const float me = ev_n;
            {
                const size_t ibn = ib0 + (size_t)tn*D_;
                al_n = __ldcs(&g_alpha[ibn]);
                ev_n = __ldcs(&evalm[ibn]);
            }
            float ch = al*zh + (1.f - al)*xh;
            cc = mv*xv + (1.f - mv)*ch;
            if (w2 == 0) {
                __stcs(&out[ib], cc);
                float p = fabsf(cc - xv) * me;
                #pragma unroll
                for (int off = 16; off > 0; off >>= 1)
                    p += __shfl_down_sync(0xffffffffu, p, off);
                if (dd == 0) atomicAdd(s_num, p);
            }
            uint32_t o = (uint32_t)(SOFF_CC + (dg*8 + r1)) * 4u;
            st_dsmem(rbA + o, cc); st_dsmem(rbB + o, cc);
        }
        CLUSTER_SYNC_();

        // ---- P3: gates; half w2 covers 192 combined-k; own column = id ----
        if (tid == 0) {
            atomicAdd(&g_num[t], s_num[0]);
            s_num[0] = 0.f;
        }
        {
            ull acc[4];
            if (w2 == 0) {
                acc[0] = pack2(g8[0], g8[1]); acc[1] = pack2(g8[2], g8[3]);
                acc[2] = pack2(g8[4], g8[5]); acc[3] = pack2(g8[6], g8[7]);
            } else {
                acc[0] = 0; acc[1] = 0; acc[2] = 0; acc[3] = 0;
            }
            const float* hdp = &s_hdA[par*2048];
            if (w2 == 0) {
                // hd k 0..191
                #pragma unroll 16
                for (int k = 0; k < 192; k++) {
                    ull ww = bcast2(wp[k*256]);
                    ulonglong2 u = *(const ulonglong2*)(hdp + k*8);
                    ulonglong2 v = *(const ulonglong2*)(hdp + k*8 + 4);
                    FMA2(acc[0], u.x, ww, acc[0]);
                    FMA2(acc[1], u.y, ww, acc[1]);
                    FMA2(acc[2], v.x, ww, acc[2]);
                    FMA2(acc[3], v.y, ww, acc[3]);
                }
            } else {
                // hd k 192..255
                #pragma unroll 16
                for (int k = 192; k < 256; k++) {
                    ull ww = bcast2(wp[k*256]);
                    ulonglong2 u = *(const ulonglong2*)(hdp + k*8);
                    ulonglong2 v = *(const ulonglong2*)(hdp + k*8 + 4);
                    FMA2(acc[0], u.x, ww, acc[0]);
                    FMA2(acc[1], u.y, ww, acc[1]);
                    FMA2(acc[2], v.x, ww, acc[2]);
                    FMA2(acc[3], v.y, ww, acc[3]);
                }
                // cc k' 0..127 (combined k 256..383)
                const float* wpc = wp + 256*256;
                #pragma unroll 16
                for (int k = 0; k < 128; k++) {
                    ull ww = bcast2(wpc[k*256]);
                    ulonglong2 u = *(const ulonglong2*)(s_cc + k*8);
                    ulonglong2 v = *(const ulonglong2*)(s_cc + k*8 + 4);
                    FMA2(acc[0], u.x, ww, acc[0]);
                    FMA2(acc[1], u.y, ww, acc[1]);
                    FMA2(acc[2], v.x, ww, acc[2]);
                    FMA2(acc[3], v.y, ww, acc[3]);
                }
                // publish half-1 partials
                #pragma unroll
                for (int rp = 0; rp < 4; rp++) {
                    float2 u = unpack2(acc[rp]);
                    s_red[(2*rp    )*256 + id] = u.x;
                    s_red[(2*rp + 1)*256 + id] = u.y;
                }
            }
            __syncthreads();
            if (w2 == 0) {
                #pragma unroll
                for (int rp = 0; rp < 4; rp++) {
                    float2 u = unpack2(acc[rp]);
                    s_gt[(2*rp    )*256 + id] = u.x + s_red[(2*rp    )*256 + id];
                    s_gt[(2*rp + 1)*256 + id] = u.y + s_red[(2*rp + 1)*256 + id];
                }
            }
        }
        __syncthreads();

        // ---- P4: LSTM elementwise (both halves mirror state) ----
        {
            const float* gr = &s_gt[r1*256];
            float2 ii = *(const float2*)(gr + jjA);
            float2 ff = *(const float2*)(gr + 64 + jjA);
            float2 gv = *(const float2*)(gr + 128 + jjA);
            float2 oo = *(const float2*)(gr + 192 + jjA);
            float i0 = sigm_(ii.x), f0 = sigm_(ff.x), o0 = sigm_(oo.x), g0 = tanh_(gv.x);
            float i1 = sigm_(ii.y), f1 = sigm_(ff.y), o1 = sigm_(oo.y), g1 = tanh_(gv.y);
            cA = f0*cA + i0*g0;  hA = o0 * tanh_(cA);
            cB = f1*cB + i1*g1;  hB = o1 * tanh_(cB);
        }
        // s_hdA double-buffered; s_hdB/s_xcB/s_cc/s_gt/s_red rewrites are
        // separated by >=1 barrier from their last reads.
    }
}

// ---------------- K5: finalize loss -------------------------------------------------
__global__ void k_fin(float* __restrict__ out, int out_size)
{
    int t = threadIdx.x;
    float v = g_num[t] / (g_den[t] + 1e-5f);
    #pragma unroll
    for (int off = 16; off > 0; off >>= 1)
        v += __shfl_down_sync(0xffffffffu, v, off);
    __shared__ float red[8];
    if ((t & 31) == 0) red[t >> 5] = v;
    __syncthreads();
    if (t == 0) {
        float s = 0.f;
        #pragma unroll
        for (int i = 0; i < 8; i++) s += red[i];
        if (out_size > B_*L_*D_) out[B_*L_*D_] = s;
    }
}

// ---------------- launch -------------------------------------------------------------
extern "C" void kernel_launch(void* const* d_in, const int* in_sizes, int n_in,
                              void* d_out, int out_size)
{
    const float* values = (const float*)d_in[0];
    const float* masks  = (const float*)d_in[1];
    const float* deltas = (const float*)d_in[2];
    const float* evalm  = (const float*)d_in[3];
    const float* td_h_W = (const float*)d_in[4];
    const float* td_h_b = (const float*)d_in[5];
    const float* td_x_w = (const float*)d_in[6];
    const float* td_x_b = (const float*)d_in[7];
    const float* hist_W = (const float*)d_in[8];
    const float* hist_b = (const float*)d_in[9];
    const float* feat_W = (const float*)d_in[10];
    const float* feat_b = (const float*)d_in[11];
    const float* wc_W   = (const float*)d_in[12];
    const float* wc_b   = (const float*)d_in[13];
    const float* W_ih   = (const float*)d_in[14];
    const float* W_hh   = (const float*)d_in[15];
    const float* b_ih   = (const float*)d_in[16];
    const float* b_hh   = (const float*)d_in[17];
    float* out = (float*)d_out;

    cudaFuncSetAttribute(k_main4, cudaFuncAttributeMaxDynamicSharedMemorySize, SMEM_BYTES);

    k_prep   <<<256, 256>>>(W_ih, W_hh, td_h_W, wc_W, b_ih, b_hh);
    k_den    <<<L_, 128>>>(evalm);
    k_gamma_h<<<BL_/16, 256>>>(deltas, td_h_b);
    k_alpha  <<<BL_/16, 128>>>(deltas, masks, td_x_w, td_x_b, wc_b);
    k_gpre   <<<BL_/16, 512>>>(masks);
    k_main4  <<<128, 512, SMEM_BYTES>>>(values, masks, evalm, hist_W, feat_W,
                                        hist_b, feat_b, out);
    k_fin    <<<1, 256>>>(out, out_size);
}

// round 12
// speedup vs baseline: 1.6432x; 1.0025x over previous
#include <cuda_runtime.h>
#include <math.h>
#include <stdint.h>

#define B_  256
#define L_  256
#define D_  128
#define H_  256
#define G4_ 1024
#define BL_ (B_*L_)
#define KC_ 384                      // combined k: 256 (Whh) + 128 (WihA)

typedef unsigned long long ull;

// ---------------- f32x2 helpers ---------------------------------------------------
#define FMA2(d,a,b,c) asm("fma.rn.f32x2 %0, %1, %2, %3;" : "=l"(d) : "l"(a), "l"(b), "l"(c))
__device__ __forceinline__ ull bcast2(float v){ ull d; asm("mov.b64 %0, {%1, %1};" : "=l"(d) : "f"(v)); return d; }
__device__ __forceinline__ ull pack2(float lo, float hi){ ull d; asm("mov.b64 %0, {%1, %2};" : "=l"(d) : "f"(lo), "f"(hi)); return d; }
__device__ __forceinline__ float2 unpack2(ull d){ float lo,hi; asm("mov.b64 {%0, %1}, %2;" : "=f"(lo), "=f"(hi) : "l"(d)); return make_float2(lo,hi); }

// ---------------- device scratch (static; no allocations anywhere) ----------------
__device__ float g_gamma_h[BL_*H_];            // 64 MB
__device__ float g_alpha  [BL_*D_];            // 32 MB
// cluster-grouped: [bg(32)][t(256)][q(4)][r(8)][nn(256)]
__device__ float g_gpre   [(size_t)BL_*G4_];   // 256 MB
// combined weights, PAIR-INTERLEAVED per CTA: [q(4)][kp(192)][nn(256)][2]
// k = 2*kp + s ; k<256: Whh[permN(q*256+nn)][k] ; k>=256: W_ih[permN(..)][k-256]
__device__ float g_Wcomb  [4*KC_*256];
__device__ float g_WihB_t [D_*G4_];            // [k][n'] permuted (for k_gpre)
__device__ float g_tdh_t  [D_*H_];             // [d][j]
__device__ float g_wc_t   [(2*D_)*D_];         // [k][dn]
__device__ float g_bias   [G4_];               // permuted b_ih+b_hh
__device__ float g_num    [L_];
__device__ float g_den    [L_];

// gate-column permutation: n' = q*256 + g*64 + jj  <->  n = g*256 + q*64 + jj
__device__ __forceinline__ int permN(int np) {
    return ((np >> 6) & 3) * 256 + (np >> 8) * 64 + (np & 63);
}

// ---------------- K0: weight transposes (permuted) + zero g_num -------------------
__global__ void k_prep(const float* __restrict__ W_ih,   const float* __restrict__ W_hh,
                       const float* __restrict__ td_h_W, const float* __restrict__ wc_W,
                       const float* __restrict__ b_ih,   const float* __restrict__ b_hh)
{
    int idx = blockIdx.x * blockDim.x + threadIdx.x;
    int stride = gridDim.x * blockDim.x;
    for (int i = idx; i < 4*KC_*256; i += stride) {
        int q = i / (KC_*256);
        int rem = i % (KC_*256);
        int kp = rem >> 9;               // pair index 0..191
        int r2 = rem & 511;
        int nn = r2 >> 1, s = r2 & 1;
        int k = 2*kp + s;
        int n = permN(q*256 + nn);
        g_Wcomb[i] = (k < 256) ? W_hh[n*H_ + k] : W_ih[n*(2*D_) + (k - 256)];
    }
    for (int i = idx; i < D_*G4_; i += stride) {
        int k = i >> 10, np = i & 1023;
        int n = permN(np);
        g_WihB_t[i] = W_ih[n*(2*D_) + D_ + k];
    }
    for (int i = idx; i < D_*H_; i += stride) {
        int d = i / H_, j = i % H_;
        g_tdh_t[i] = td_h_W[j*D_ + d];
    }
    for (int i = idx; i < (2*D_)*D_; i += stride) {
        int k = i / D_, dn = i % D_;
        g_wc_t[i] = wc_W[dn*(2*D_) + k];
    }
    for (int i = idx; i < G4_; i += stride) {
        int n = permN(i);
        g_bias[i] = b_ih[n] + b_hh[n];
    }
    for (int i = idx; i < L_;  i += stride) g_num[i] = 0.f;
}

// ---------------- K0b: per-timestep loss denominator ------------------------------
__global__ void k_den(const float* __restrict__ evalm)
{
    int t = blockIdx.x;
    int tid = threadIdx.x;
    float s = 0.f;
    for (int b = 0; b < B_; b++)
        s += evalm[((size_t)b*L_ + t)*D_ + tid];
    #pragma unroll
    for (int off = 16; off > 0; off >>= 1)
        s += __shfl_down_sync(0xffffffffu, s, off);
    __shared__ float red[4];
    if ((tid & 31) == 0) red[tid >> 5] = s;
    __syncthreads();
    if (tid == 0) g_den[t] = red[0] + red[1] + red[2] + red[3];
}

// ---------------- K1: gamma_h precompute -------------------------------------------
__global__ void __launch_bounds__(256) k_gamma_h(const float* __restrict__ deltas,
                                                 const float* __restrict__ td_h_b)
{
    __shared__ float sd[16][D_];
    int bl0 = blockIdx.x * 16;
    int tid = threadIdx.x;
    #pragma unroll
    for (int i = 0; i < 8; i++) {
        int idx = tid + i*256;
        int r = idx >> 7, d = idx & 127;
        sd[r][d] = deltas[(size_t)(bl0 + r)*D_ + d];
    }
    __syncthreads();
    int j = tid;
    float acc[16];
    float b = td_h_b[j];
    #pragma unroll
    for (int r = 0; r < 16; r++) acc[r] = b;
    #pragma unroll 4
    for (int d = 0; d < D_; d++) {
        float w = g_tdh_t[d*H_ + j];
        #pragma unroll
        for (int r = 0; r < 16; r++) acc[r] += sd[r][d] * w;
    }
    #pragma unroll
    for (int r = 0; r < 16; r++)
        g_gamma_h[(size_t)(bl0 + r)*H_ + j] = __expf(-fmaxf(acc[r], 0.f));
}

// ---------------- K2: alpha precompute ---------------------------------------------
__global__ void __launch_bounds__(128) k_alpha(const float* __restrict__ deltas,
                                               const float* __restrict__ masks,
                                               const float* __restrict__ td_x_w,
                                               const float* __restrict__ td_x_b,
                                               const float* __restrict__ wc_b)
{
    __shared__ float sin_[16][2*D_];
    int bl0 = blockIdx.x * 16;
    int tid = threadIdx.x;
    #pragma unroll
    for (int i = 0; i < 32; i++) {
        int idx = tid + i*128;
        int r = idx >> 8, k = idx & 255;
        float v;
        if (k < D_) {
            float dd = deltas[(size_t)(bl0 + r)*D_ + k];
            v = __expf(-fmaxf(dd*td_x_w[k] + td_x_b[k], 0.f));
        } else {
            v = masks[(size_t)(bl0 + r)*D_ + (k - D_)];
        }
        sin_[r][k] = v;
    }
    __syncthreads();
    int dn = tid;
    float acc[16];
    float b = wc_b[dn];
    #pragma unroll
    for (int r = 0; r < 16; r++) acc[r] = b;
    #pragma unroll 4
    for (int k = 0; k < 2*D_; k++) {
        float w = g_wc_t[k*D_ + dn];
        #pragma unroll
        for (int r = 0; r < 16; r++) acc[r] += sin_[r][k] * w;
    }
    #pragma unroll
    for (int r = 0; r < 16; r++)
        g_alpha[(size_t)(bl0 + r)*D_ + dn] = acc[r];
}

// ---------------- K3: gates m-half precompute (16 rows/CTA) -------------------------
__global__ void __launch_bounds__(512) k_gpre(const float* __restrict__ masks)
{
    __shared__ float sm[D_*16];     // [d][row16]
    int bl0 = blockIdx.x * 16;
    int tid = threadIdx.x;
    #pragma unroll
    for (int i = 0; i < 4; i++) {
        int idx = tid + i*512;
        int r = idx >> 7, d = idx & 127;
        sm[d*16 + r] = masks[(size_t)(bl0 + r)*D_ + d];
    }
    __syncthreads();
    int n2 = tid * 2;
    float2 b2 = *(const float2*)&g_bias[n2];
    ull acc[8][2];
    #pragma unroll
    for (int rp = 0; rp < 8; rp++) { acc[rp][0] = bcast2(b2.x); acc[rp][1] = bcast2(b2.y); }
    #pragma unroll 2
    for (int k = 0; k < D_; k++) {
        float2 w = *(const float2*)&g_WihB_t[k*G4_ + n2];
        ull pw0 = bcast2(w.x), pw1 = bcast2(w.y);
        const ulonglong2* mrow = (const ulonglong2*)&sm[k*16];
        ulonglong2 m0 = mrow[0], m1 = mrow[1], m2 = mrow[2], m3 = mrow[3];
        FMA2(acc[0][0], m0.x, pw0, acc[0][0]); FMA2(acc[0][1], m0.x, pw1, acc[0][1]);
        FMA2(acc[1][0], m0.y, pw0, acc[1][0]); FMA2(acc[1][1], m0.y, pw1, acc[1][1]);
        FMA2(acc[2][0], m1.x, pw0, acc[2][0]); FMA2(acc[2][1], m1.x, pw1, acc[2][1]);
        FMA2(acc[3][0], m1.y, pw0, acc[3][0]); FMA2(acc[3][1], m1.y, pw1, acc[3][1]);
        FMA2(acc[4][0], m2.x, pw0, acc[4][0]); FMA2(acc[4][1], m2.x, pw1, acc[4][1]);
        FMA2(acc[5][0], m2.y, pw0, acc[5][0]); FMA2(acc[5][1], m2.y, pw1, acc[5][1]);
        FMA2(acc[6][0], m3.x, pw0, acc[6][0]); FMA2(acc[6][1], m3.x, pw1, acc[6][1]);
        FMA2(acc[7][0], m3.y, pw0, acc[7][0]); FMA2(acc[7][1], m3.y, pw1, acc[7][1]);
    }
    int b = bl0 >> 8, t0c = bl0 & 255;
    int bg = b >> 3, rr = b & 7;
    int q = n2 >> 8, nn = n2 & 255;
    #pragma unroll
    for (int rp = 0; rp < 8; rp++) {
        float2 u0 = unpack2(acc[rp][0]), u1 = unpack2(acc[rp][1]);
        float2 lo = make_float2(u0.x, u1.x);
        float2 hi = make_float2(u0.y, u1.y);
        size_t aLo = ((((size_t)bg*256 + t0c + 2*rp    )*4 + q)*8 + rr)*256 + nn;
        size_t aHi = ((((size_t)bg*256 + t0c + 2*rp + 1)*4 + q)*8 + rr)*256 + nn;
        *(float2*)&g_gpre[aLo] = lo;
        *(float2*)&g_gpre[aHi] = hi;
    }
}

// ---------------- DSMEM helpers -----------------------------------------------------
__device__ __forceinline__ uint32_t smem_u32_(const void* p) {
    uint32_t a;
    asm("{ .reg .u64 t; cvta.to.shared.u64 t, %1; cvt.u32.u64 %0, t; }"
        : "=r"(a) : "l"(p));
    return a;
}
__device__ __forceinline__ void st_dsmem(uint32_t addr, float v) {
    asm volatile("st.shared::cluster.f32 [%0], %1;" :: "r"(addr), "f"(v) : "memory");
}
__device__ __forceinline__ void st_dsmem64(uint32_t addr, ull v) {
    asm volatile("st.shared::cluster.b64 [%0], %1;" :: "r"(addr), "l"(v) : "memory");
}
#define CLUSTER_SYNC_() do { \
    asm volatile("barrier.cluster.arrive.aligned;" ::: "memory"); \
    asm volatile("barrier.cluster.wait.aligned;"  ::: "memory"); } while (0)

// SMEM layout (floats)
#define HIST_STRIDE 260
#define FEAT_STRIDE 132
#define SOFF_HISTT 0                                     // 32*260 = 8320
#define SOFF_FEATT (SOFF_HISTT + 32*HIST_STRIDE)         // 8320
#define SOFF_HDA   (SOFF_FEATT + 32*FEAT_STRIDE)         // 12544
#define SOFF_HDB   (SOFF_HDA + 2*256*8)                  // 16640
#define SOFF_XCB   (SOFF_HDB + 8*256)                    // 18688
#define SOFF_CC    (SOFF_XCB + 8*128)                    // 19712
#define SOFF_GT    (SOFF_CC + 128*8)                     // 20736
#define SOFF_RED   (SOFF_GT + 8*256)                     // 22784  [8][256] scratch
#define SOFF_NUM   (SOFF_RED + 8*256)                    // 24832
#define SMEM_FLOATS (SOFF_NUM + 16)
#define SMEM_BYTES (SMEM_FLOATS * 4)

__device__ __forceinline__ float sigm_(float x) { return 1.f / (1.f + __expf(-x)); }
__device__ __forceinline__ float tanh_(float x) { return 2.f / (1.f + __expf(-2.f*x)) - 1.f; }

// ---------------- K4: cluster-4 recurrence, 512 threads, paired weight LDG ----------
__global__ void __launch_bounds__(512) __cluster_dims__(4, 1, 1)
k_main4(const float* __restrict__ values, const float* __restrict__ masks,
        const float* __restrict__ evalm,
        const float* __restrict__ hist_W, const float* __restrict__ feat_W,
        const float* __restrict__ hist_b, const float* __restrict__ feat_b,
        float* __restrict__ out)
{
    extern __shared__ float smf[];
    float* s_histT = smf + SOFF_HISTT;   // [32][260]
    float* s_featT = smf + SOFF_FEATT;   // [32][132]
    float* s_hdA   = smf + SOFF_HDA;     // [2][256][8]
    float* s_hdB   = smf + SOFF_HDB;     // [8][256]
    float* s_xcB   = smf + SOFF_XCB;     // [8][128]
    float* s_cc    = smf + SOFF_CC;      // [128][8]
    float* s_gt    = smf + SOFF_GT;      // [8][256]
    float* s_red   = smf + SOFF_RED;     // [8][256] reduction scratch
    float* s_num   = smf + SOFF_NUM;

    const int tid = threadIdx.x;
    const int id  = tid & 255;           // phase-local index
    const int w2  = tid >> 8;            // k-half 0/1
    uint32_t q;
    asm("mov.u32 %0, %%cluster_ctarank;" : "=r"(q));
    const int bg = blockIdx.x >> 2;
    const int b0 = bg * 8;

    // --- preload stationary hist/feat slices ---
    #pragma unroll 4
    for (int i = tid; i < 32*256; i += 512) {
        int dd = i >> 8, k = i & 255;
        s_histT[dd*HIST_STRIDE + k] = hist_W[((int)q*32 + dd)*H_ + k];
    }
    #pragma unroll 2
    for (int i = tid; i < 32*128; i += 512) {
        int dd = i >> 7, k = i & 127;
        int dgx = (int)q*32 + dd;
        s_featT[dd*FEAT_STRIDE + k] = (k == dgx) ? 0.f : feat_W[dgx*D_ + k];
    }
    if (tid == 0) s_num[0] = 0.f;
    __syncthreads();

    // remote SMEM bases: this half pushes to 2 ranks (w2=0 -> 0,1 ; w2=1 -> 2,3)
    uint32_t sbase = smem_u32_(smf);
    uint32_t rbA, rbB;
    asm("mapa.shared::cluster.u32 %0, %1, %2;" : "=r"(rbA) : "r"(sbase), "r"((uint32_t)(2*w2)));
    asm("mapa.shared::cluster.u32 %0, %1, %2;" : "=r"(rbB) : "r"(sbase), "r"((uint32_t)(2*w2 + 1)));

    // thread mappings
    const int r1 = id >> 5;                  // batch row 0..7
    const int dd = id & 31;                  // within-slice d
    const int dg = (int)q*32 + dd;           // global d
    const int jjA = dd*2;                    // two owned (local) h-indices
    const int jgA = (int)q*64 + jjA;         // global h index
    const float hb = hist_b[dg], fb = feat_b[dg];

    const size_t ib0   = ((size_t)(b0+r1)*L_)*D_ + dg;
    const size_t gam0  = ((size_t)(b0+r1)*L_)*H_ + jgA;
    const float* wp2   = g_Wcomb + ((size_t)q)*KC_*256 + id*2;   // + kp*512
    const float* gp0   = g_gpre + (((size_t)bg*256*4 + q)*8)*256 + id;

    float hA = 0.f, hB = 0.f, cA = 0.f, cB = 0.f;   // mirrored in both halves

    float2 gg   = __ldcs((const float2*)&g_gamma_h[gam0]);
    float  xv_n = __ldcs(&values[ib0]);
    float  mv_n = __ldcs(&masks[ib0]);
    float  al_n = __ldcs(&g_alpha[ib0]);
    float  ev_n = __ldcs(&evalm[ib0]);

    for (int t = 0; t < L_; t++) {
        const int par = t & 1;
        const int tn = (t + 1) & 255;

        // ---- gpre prefetch (w2==0 only; consumed in P3) ----
        float g8[8];
        if (w2 == 0) {
            const float* gp = gp0 + (size_t)t*(4*8*256);
            #pragma unroll
            for (int r = 0; r < 8; r++) g8[r] = __ldcs(gp + r*256);
        }

        // ---- P0: decay h, push hd to this half's 2 ranks ----
        {
            float hdA = hA * gg.x;
            float hdB = hB * gg.y;
            uint32_t oA = (uint32_t)(SOFF_HDA + ((par*256 + jgA)*8 + r1)) * 4u;
            uint32_t oA2 = oA + 32u;
            ull hp = pack2(hdA, hdB);
            uint32_t oB = (uint32_t)(SOFF_HDB + (r1*256 + jgA)) * 4u;
            st_dsmem(rbA + oA, hdA); st_dsmem(rbA + oA2, hdB); st_dsmem64(rbA + oB, hp);
            st_dsmem(rbB + oA, hdA); st_dsmem(rbB + oA2, hdB); st_dsmem64(rbB + oB, hp);
            gg = __ldcs((const float2*)&g_gamma_h[gam0 + (size_t)tn*H_]);
        }
        CLUSTER_SYNC_();

        // ---- P1: partial x_h over k-half [128*w2, 128*w2+128) ----
        const size_t ib = ib0 + (size_t)t*D_;
        const float xv = xv_n;
        const float mv = mv_n;
        {
            const size_t ibn = ib0 + (size_t)tn*D_;
            xv_n = __ldcs(&values[ibn]);
            mv_n = __ldcs(&masks[ibn]);
        }
        {
            const float* hp = &s_hdB[r1*256 + w2*128];
            const float* wpt = &s_histT[dd*HIST_STRIDE + w2*128];
            ull a0 = 0, a1 = 0, a2 = 0, a3 = 0;
            #pragma unroll 8
            for (int k = 0; k < 128; k += 8) {
                ulonglong2 hv  = *(const ulonglong2*)(hp + k);
                ulonglong2 hv2 = *(const ulonglong2*)(hp + k + 4);
                ulonglong2 wv  = *(const ulonglong2*)(wpt + k);
                ulonglong2 wv2 = *(const ulonglong2*)(wpt + k + 4);
                FMA2(a0, hv.x,  wv.x,  a0);
                FMA2(a1, hv.y,  wv.y,  a1);
                FMA2(a2, hv2.x, wv2.x, a2);
                FMA2(a3, hv2.y, wv2.y, a3);
            }
            float2 p0 = unpack2(a0), p1 = unpack2(a1), p2 = unpack2(a2), p3 = unpack2(a3);
            float part = ((p0.x + p0.y) + (p1.x + p1.y)) + ((p2.x + p2.y) + (p3.x + p3.y));
            if (w2 == 0) part += hb;
            s_red[w2*256 + id] = part;
        }
        __syncthreads();
        const float xh = s_red[id] + s_red[256 + id];
        const float xc = mv*xv + (1.f - mv)*xh;
        {
            uint32_t o = (uint32_t)(SOFF_XCB + (r1*128 + dg)) * 4u;
            st_dsmem(rbA + o, xc); st_dsmem(rbB + o, xc);
        }
        CLUSTER_SYNC_();

        // ---- P2: partial z_h over k-half [64*w2, 64*w2+64) ----
        float cc;
        {
            const float* xp = &s_xcB[r1*128 + w2*64];
            const float* wpt = &s_featT[dd*FEAT_STRIDE + w2*64];
            ull a0 = 0, a1 = 0;
            #pragma unroll 8
            for (int k = 0; k < 64; k += 4) {
                ulonglong2 xv2 = *(const ulonglong2*)(xp + k);
                ulonglong2 wv2 = *(const ulonglong2*)(wpt + k);
                FMA2(a0, xv2.x, wv2.x, a0);
                FMA2(a1, xv2.y, wv2.y, a1);
            }
            float2 p0 = unpack2(a0), p1 = unpack2(a1);
            float part = (p0.x + p0.y) + (p1.x + p1.y);
            if (w2 == 0) part += fb;
            s_red[w2*256 + id] = part;
        }
        __syncthreads();
        {
            const float zh = s_red[id] + s_red[256 + id];
            const float al = al_n;
            const float me = ev_n;
            {
                const size_t ibn = ib0 + (size_t)tn*D_;
                al_n = __ldcs(&g_alpha[ibn]);
                ev_n = __ldcs(&evalm[ibn]);
            }
            float ch = al*zh + (1.f - al)*xh;
            cc = mv*xv + (1.f - mv)*ch;
            if (w2 == 0) {
                __stcs(&out[ib], cc);
                float p = fabsf(cc - xv) * me;
                #pragma unroll
                for (int off = 16; off > 0; off >>= 1)
                    p += __shfl_down_sync(0xffffffffu, p, off);
                if (dd == 0) atomicAdd(s_num, p);
            }
            uint32_t o = (uint32_t)(SOFF_CC + (dg*8 + r1)) * 4u;
            st_dsmem(rbA + o, cc); st_dsmem(rbB + o, cc);
        }
        CLUSTER_SYNC_();

        // ---- P3: gates; paired-k weight LDG.64; half w2 covers 192 combined-k ----
        if (tid == 0) {
            atomicAdd(&g_num[t], s_num[0]);
            s_num[0] = 0.f;
        }
        {
            ull acc[4];
            if (w2 == 0) {
                acc[0] = pack2(g8[0], g8[1]); acc[1] = pack2(g8[2], g8[3]);
                acc[2] = pack2(g8[4], g8[5]); acc[3] = pack2(g8[6], g8[7]);
            } else {
                acc[0] = 0; acc[1] = 0; acc[2] = 0; acc[3] = 0;
            }
            const float* hdp = &s_hdA[par*2048];
            if (w2 == 0) {
                // hd k 0..191  (pairs 0..95)
                #pragma unroll 8
                for (int kp = 0; kp < 96; kp++) {
                    float2 wf = unpack2(*(const ull*)(wp2 + kp*512));
                    ull wwa = bcast2(wf.x), wwb = bcast2(wf.y);
                    const float* h0 = hdp + kp*16;
                    ulonglong2 u0 = *(const ulonglong2*)(h0);
                    ulonglong2 v0 = *(const ulonglong2*)(h0 + 4);
                    ulonglong2 u1 = *(const ulonglong2*)(h0 + 8);
                    ulonglong2 v1 = *(const ulonglong2*)(h0 + 12);
                    FMA2(acc[0], u0.x, wwa, acc[0]);
                    FMA2(acc[1], u0.y, wwa, acc[1]);
                    FMA2(acc[2], v0.x, wwa, acc[2]);
                    FMA2(acc[3], v0.y, wwa, acc[3]);
                    FMA2(acc[0], u1.x, wwb, acc[0]);
                    FMA2(acc[1], u1.y, wwb, acc[1]);
                    FMA2(acc[2], v1.x, wwb, acc[2]);
                    FMA2(acc[3], v1.y, wwb, acc[3]);
                }
            } else {
                // hd k 192..255  (pairs 96..127)
                #pragma unroll 8
                for (int kp = 96; kp < 128; kp++) {
                    float2 wf = unpack2(*(const ull*)(wp2 + kp*512));
                    ull wwa = bcast2(wf.x), wwb = bcast2(wf.y);
                    const float* h0 = hdp + kp*16;
                    ulonglong2 u0 = *(const ulonglong2*)(h0);
                    ulonglong2 v0 = *(const ulonglong2*)(h0 + 4);
                    ulonglong2 u1 = *(const ulonglong2*)(h0 + 8);
                    ulonglong2 v1 = *(const ulonglong2*)(h0 + 12);
                    FMA2(acc[0], u0.x, wwa, acc[0]);
                    FMA2(acc[1], u0.y, wwa, acc[1]);
                    FMA2(acc[2], v0.x, wwa, acc[2]);
                    FMA2(acc[3], v0.y, wwa, acc[3]);
                    FMA2(acc[0], u1.x, wwb, acc[0]);
                    FMA2(acc[1], u1.y, wwb, acc[1]);
                    FMA2(acc[2], v1.x, wwb, acc[2]);
                    FMA2(acc[3], v1.y, wwb, acc[3]);
                }
                // cc k' 0..127 (combined pairs 128..191)
                #pragma unroll 8
                for (int kp = 0; kp < 64; kp++) {
                    float2 wf = unpack2(*(const ull*)(wp2 + (128 + kp)*512));
                    ull wwa = bcast2(wf.x), wwb = bcast2(wf.y);
                    const float* c0 = s_cc + kp*16;
                    ulonglong2 u0 = *(const ulonglong2*)(c0);
                    ulonglong2 v0 = *(const ulonglong2*)(c0 + 4);
                    ulonglong2 u1 = *(const ulonglong2*)(c0 + 8);
                    ulonglong2 v1 = *(const ulonglong2*)(c0 + 12);
                    FMA2(acc[0], u0.x, wwa, acc[0]);
                    FMA2(acc[1], u0.y, wwa, acc[1]);
                    FMA2(acc[2], v0.x, wwa, acc[2]);
                    FMA2(acc[3], v0.y, wwa, acc[3]);
                    FMA2(acc[0], u1.x, wwb, acc[0]);
                    FMA2(acc[1], u1.y, wwb, acc[1]);
                    FMA2(acc[2], v1.x, wwb, acc[2]);
                    FMA2(acc[3], v1.y, wwb, acc[3]);
                }
                // publish half-1 partials
                #pragma unroll
                for (int rp = 0; rp < 4; rp++) {
                    float2 u = unpack2(acc[rp]);
                    s_red[(2*rp    )*256 + id] = u.x;
                    s_red[(2*rp + 1)*256 + id] = u.y;
                }
            }
            __syncthreads();
            if (w2 == 0) {
                #pragma unroll
                for (int rp = 0; rp < 4; rp++) {
                    float2 u = unpack2(acc[rp]);
                    s_gt[(2*rp    )*256 + id] = u.x + s_red[(2*rp    )*256 + id];
                    s_gt[(2*rp + 1)*256 + id] = u.y + s_red[(2*rp + 1)*256 + id];
                }
            }
        }
        __syncthreads();

        // ---- P4: LSTM elementwise (both halves mirror state) ----
        {
            const float* gr = &s_gt[r1*256];
            float2 ii = *(const float2*)(gr + jjA);
            float2 ff = *(const float2*)(gr + 64 + jjA);
            float2 gv = *(const float2*)(gr + 128 + jjA);
            float2 oo = *(const float2*)(gr + 192 + jjA);
            float i0 = sigm_(ii.x), f0 = sigm_(ff.x), o0 = sigm_(oo.x), g0 = tanh_(gv.x);
            float i1 = sigm_(ii.y), f1 = sigm_(ff.y), o1 = sigm_(oo.y), g1 = tanh_(gv.y);
            cA = f0*cA + i0*g0;  hA = o0 * tanh_(cA);
            cB = f1*cB + i1*g1;  hB = o1 * tanh_(cB);
        }
        // s_hdA double-buffered; s_hdB/s_xcB/s_cc/s_gt/s_red rewrites are
        // separated by >=1 barrier from their last reads.
    }
}

// ---------------- K5: finalize loss -------------------------------------------------
__global__ void k_fin(float* __restrict__ out, int out_size)
{
    int t = threadIdx.x;
    float v = g_num[t] / (g_den[t] + 1e-5f);
    #pragma unroll
    for (int off = 16; off > 0; off >>= 1)
        v += __shfl_down_sync(0xffffffffu, v, off);
    __shared__ float red[8];
    if ((t & 31) == 0) red[t >> 5] = v;
    __syncthreads();
    if (t == 0) {
        float s = 0.f;
        #pragma unroll
        for (int i = 0; i < 8; i++) s += red[i];
        if (out_size > B_*L_*D_) out[B_*L_*D_] = s;
    }
}

// ---------------- launch -------------------------------------------------------------
extern "C" void kernel_launch(void* const* d_in, const int* in_sizes, int n_in,
                              void* d_out, int out_size)
{
    const float* values = (const float*)d_in[0];
    const float* masks  = (const float*)d_in[1];
    const float* deltas = (const float*)d_in[2];
    const float* evalm  = (const float*)d_in[3];
    const float* td_h_W = (const float*)d_in[4];
    const float* td_h_b = (const float*)d_in[5];
    const float* td_x_w = (const float*)d_in[6];
    const float* td_x_b = (const float*)d_in[7];
    const float* hist_W = (const float*)d_in[8];
    const float* hist_b = (const float*)d_in[9];
    const float* feat_W = (const float*)d_in[10];
    const float* feat_b = (const float*)d_in[11];
    const float* wc_W   = (const float*)d_in[12];
    const float* wc_b   = (const float*)d_in[13];
    const float* W_ih   = (const float*)d_in[14];
    const float* W_hh   = (const float*)d_in[15];
    const float* b_ih   = (const float*)d_in[16];
    const float* b_hh   = (const float*)d_in[17];
    float* out = (float*)d_out;

    cudaFuncSetAttribute(k_main4, cudaFuncAttributeMaxDynamicSharedMemorySize, SMEM_BYTES);

    k_prep   <<<256, 256>>>(W_ih, W_hh, td_h_W, wc_W, b_ih, b_hh);
    k_den    <<<L_, 128>>>(evalm);
    k_gamma_h<<<BL_/16, 256>>>(deltas, td_h_b);
    k_alpha  <<<BL_/16, 128>>>(deltas, masks, td_x_w, td_x_b, wc_b);
    k_gpre   <<<BL_/16, 512>>>(masks);
    k_main4  <<<128, 512, SMEM_BYTES>>>(values, masks, evalm, hist_W, feat_W,
                                        hist_b, feat_b, out);
    k_fin    <<<1, 256>>>(out, out_size);
}